// round 1
// baseline (speedup 1.0000x reference)
#include <cuda_runtime.h>
#include <cuda_bf16.h>

#define NN 1024
#define HH 64
#define EE 16384

// ---------------- scratch (device globals; no allocation) ----------------
__device__ __align__(16) float g_hg1[NN*HH], g_ha1[NN*HH], g_hg2[NN*HH], g_ha2[NN*HH], g_hg3[NN*HH];
__device__ __align__(16) float g_xa1[NN*HH], g_xd1[NN*HH], g_xa2[NN*HH], g_xd2[NN*HH], g_h3[NN*HH];
__device__ __align__(16) float g_h1p[NN*HH], g_h2p[NN*HH];
__device__ float g_als1[NN], g_ald1[NN], g_als2[NN], g_ald2[NN];
__device__ float g_deg[NN], g_den1[NN], g_den2[NN], g_selfc1[NN], g_selfc2[NN];
__device__ float g_expE1[EE], g_expE2[EE];
__device__ float g_ewmean, g_c1, g_c2;

// ---------------- helpers ----------------
__device__ __forceinline__ float lrelu(float v){ return v > 0.f ? v : 0.2f*v; }

__device__ __forceinline__ void red4(float* p, float x, float y, float z, float w){
    asm volatile("red.global.add.v4.f32 [%0], {%1,%2,%3,%4};"
        :: "l"(__cvta_generic_to_global(p)), "f"(x), "f"(y), "f"(z), "f"(w) : "memory");
}

// tile GEMM: 16 nodes x 64 cols per block, 256 threads, thread = (col, rowgrp) -> 4 node-accums
template<int K, class L>
__device__ __forceinline__ void load_tile(float* xs, int n0, const L& ld){
    const int LD = K + 4;
    for (int idx = threadIdx.x; idx < 16*K; idx += 256){
        int ln = idx / K, k = idx - ln*K;
        xs[ln*LD + k] = ld(n0 + ln, k);
    }
    __syncthreads();
}

template<int K>
__device__ __forceinline__ void compute_tile(const float* xs, const float* __restrict__ W,
                                             int col, int rg, float acc[4]){
    const int LD = K + 4;
    const float* x0 = xs + rg*4*LD;
    acc[0]=0.f; acc[1]=0.f; acc[2]=0.f; acc[3]=0.f;
    #pragma unroll
    for (int k = 0; k < K; k += 4){
        float w0 = __ldg(W + (k+0)*64 + col);
        float w1 = __ldg(W + (k+1)*64 + col);
        float w2 = __ldg(W + (k+2)*64 + col);
        float w3 = __ldg(W + (k+3)*64 + col);
        #pragma unroll
        for (int i = 0; i < 4; i++){
            const float4 xv = *reinterpret_cast<const float4*>(x0 + i*LD + k);
            acc[i] = fmaf(xv.x, w0, acc[i]);
            acc[i] = fmaf(xv.y, w1, acc[i]);
            acc[i] = fmaf(xv.z, w2, acc[i]);
            acc[i] = fmaf(xv.w, w3, acc[i]);
        }
    }
}

// ---------------- loaders ----------------
struct LdRaw {
    const float* x;
    __device__ float operator()(int n, int k) const { return x[n*128 + k]; }
};
struct LdGCN {  // relu(edge_acc + (1/deg)*h_self + bias)
    const float *a, *h, *b;
    __device__ float operator()(int n, int k) const {
        float di = rsqrtf(g_deg[n]);
        return fmaxf(a[n*64+k] + di*di*h[n*64+k] + b[k], 0.f);
    }
};
struct LdGAT {  // relu(edge_acc + selfcoef*h_self + bias)
    const float *a, *h, *sc, *b;
    __device__ float operator()(int n, int k) const {
        return fmaxf(a[n*64+k] + sc[n]*h[n*64+k] + b[k], 0.f);
    }
};
struct LdMix {  // 0.7*relu(gcn2) + 0.3*relu(gat2)
    const float *bg, *bt;
    __device__ float operator()(int n, int k) const {
        float di = rsqrtf(g_deg[n]);
        float u = fmaxf(g_xa2[n*64+k] + di*di*g_hg2[n*64+k] + bg[k], 0.f);
        float v = fmaxf(g_xd2[n*64+k] + g_selfc2[n]*g_ha2[n*64+k] + bt[k], 0.f);
        return 0.7f*u + 0.3f*v;
    }
};

// ---------------- scatter helpers (4 threads/edge, float4 red) ----------------
__device__ __forceinline__ void scatter_w(const int* s_arr, const int* d_arr,
                                          const float* h, float* acc, int eb, bool gcn,
                                          const float* expE, const float* den,
                                          const float* als, const float* ald, float ewm, float c){
    int t = threadIdx.x;
    int e = eb + (t >> 2), part = t & 3;
    int s = s_arr[e], d = d_arr[e];
    float w;
    if (gcn){
        w = rsqrtf(g_deg[s]) * rsqrtf(g_deg[d]);
    } else {
        float es = expf(lrelu(als[d] + ald[d] + ewm*c));
        w = expE[e] / (den[d] + es);
    }
    const float4* hs = reinterpret_cast<const float4*>(h + s*64) + part*4;
    float* od = acc + d*64 + part*16;
    #pragma unroll
    for (int q = 0; q < 4; q++){
        float4 v = hs[q];
        red4(od + q*4, w*v.x, w*v.y, w*v.z, w*v.w);
    }
}

__device__ __forceinline__ void gat_logits(const int* s_arr, const int* d_arr, const float* ew,
                                           const float* als, const float* ald, float c,
                                           float* expE, float* den, int e){
    int s = s_arr[e], d = d_arr[e];
    float v = lrelu(als[s] + ald[d] + ew[e]*c);
    float ex = expf(v);
    expE[e] = ex;
    atomicAdd(&den[d], ex);
}

// als/ald epilogue: reduce acc[i]*att over 64 cols
__device__ __forceinline__ void attn_reduce(const float acc[4], const float* asrc, const float* adst,
                                            float* outs, float* outd, int n0, int col, int rg,
                                            float* sred /*32 floats*/){
    int t = threadIdx.x;
    if (t < 32) sred[t] = 0.f;
    __syncthreads();
    float as = asrc[col], ad = adst[col];
    float ps[4], pd[4];
    #pragma unroll
    for (int i = 0; i < 4; i++){ ps[i] = acc[i]*as; pd[i] = acc[i]*ad; }
    #pragma unroll
    for (int off = 16; off > 0; off >>= 1){
        #pragma unroll
        for (int i = 0; i < 4; i++){
            ps[i] += __shfl_down_sync(0xffffffffu, ps[i], off);
            pd[i] += __shfl_down_sync(0xffffffffu, pd[i], off);
        }
    }
    if ((t & 31) == 0){
        #pragma unroll
        for (int i = 0; i < 4; i++){
            atomicAdd(&sred[rg*4 + i], ps[i]);
            atomicAdd(&sred[16 + rg*4 + i], pd[i]);
        }
    }
    __syncthreads();
    if (t < 16){ outs[n0+t] = sred[t]; outd[n0+t] = sred[16+t]; }
}

// ---------------- kernels ----------------
// K0: zero accumulators, deg=1 (self loop), ew mean, c1/c2 scalars
__global__ __launch_bounds__(256) void k0(const float* ew, const float* we1, const float* ae1,
                                          const float* we2, const float* ae2){
    int b = blockIdx.x, t = threadIdx.x;
    if (b < 256){
        int i = b*256 + t;
        g_xa1[i]=0.f; g_xd1[i]=0.f; g_xa2[i]=0.f; g_xd2[i]=0.f; g_h3[i]=0.f;
        if (i < NN){ g_den1[i]=0.f; g_den2[i]=0.f; g_deg[i]=1.0f; }
    } else {
        __shared__ float sr[256];
        float s = 0.f;
        for (int i = t; i < EE; i += 256) s += ew[i];
        sr[t] = s; __syncthreads();
        for (int o = 128; o > 0; o >>= 1){ if (t < o) sr[t] += sr[t+o]; __syncthreads(); }
        if (t == 0) g_ewmean = sr[0] * (1.0f/EE);
        __syncthreads();
        sr[t] = (t < 64) ? we1[t]*ae1[t] : 0.f; __syncthreads();
        for (int o = 128; o > 0; o >>= 1){ if (t < o) sr[t] += sr[t+o]; __syncthreads(); }
        if (t == 0) g_c1 = sr[0];
        __syncthreads();
        sr[t] = (t < 64) ? we2[t]*ae2[t] : 0.f; __syncthreads();
        for (int o = 128; o > 0; o >>= 1){ if (t < o) sr[t] += sr[t+o]; __syncthreads(); }
        if (t == 0) g_c2 = sr[0];
    }
}

// K1: x@Wgcn1 -> hg1, x@Wgat1 -> ha1 (+als1/ald1); deg atomics
__global__ __launch_bounds__(256) void k1(const float* x, const int* eia,
                                          const float* Wg, const float* Wa,
                                          const float* asrc, const float* adst){
    __shared__ __align__(16) float xs[16*132];
    __shared__ float sred[32];
    int b = blockIdx.x, t = threadIdx.x;
    if (b < 64){
        int n0 = b*16;
        LdRaw ld{x};
        load_tile<128>(xs, n0, ld);
        int col = t & 63, rg = t >> 6;
        float acc[4];
        compute_tile<128>(xs, Wg, col, rg, acc);
        #pragma unroll
        for (int i = 0; i < 4; i++) g_hg1[(n0 + rg*4 + i)*64 + col] = acc[i];
        compute_tile<128>(xs, Wa, col, rg, acc);
        #pragma unroll
        for (int i = 0; i < 4; i++) g_ha1[(n0 + rg*4 + i)*64 + col] = acc[i];
        attn_reduce(acc, asrc, adst, g_als1, g_ald1, n0, col, rg, sred);
    } else {
        int e = (b - 64)*256 + t;
        atomicAdd(&g_deg[eia[EE + e]], 1.0f);
    }
}

// K2: GCN1 scatter; GAT1 logits/denominator
__global__ __launch_bounds__(256) void k2(const int* eia, const int* eid, const float* ew){
    int b = blockIdx.x;
    if (b < 256){
        scatter_w(eia, eia + EE, g_hg1, g_xa1, b*64, true, 0, 0, 0, 0, 0.f, 0.f);
    } else {
        int e = (b - 256)*256 + threadIdx.x;
        gat_logits(eid, eid + EE, ew, g_als1, g_ald1, g_c1, g_expE1, g_den1, e);
    }
}

// K3: GAT1 aggregate; GCN2 GEMM; selfc1
__global__ __launch_bounds__(256) void k3(const int* eid, const float* bg1, const float* Wg2){
    int b = blockIdx.x;
    if (b < 256){
        scatter_w(eid, eid + EE, g_ha1, g_xd1, b*64, false,
                  g_expE1, g_den1, g_als1, g_ald1, g_ewmean, g_c1);
    } else if (b < 320){
        __shared__ __align__(16) float xs[16*68];
        int n0 = (b - 256)*16;
        LdGCN ld{g_xa1, g_hg1, bg1};
        load_tile<64>(xs, n0, ld);
        int col = threadIdx.x & 63, rg = threadIdx.x >> 6;
        float acc[4];
        compute_tile<64>(xs, Wg2, col, rg, acc);
        #pragma unroll
        for (int i = 0; i < 4; i++) g_hg2[(n0 + rg*4 + i)*64 + col] = acc[i];
    } else {
        int n = (b - 320)*256 + threadIdx.x;
        float es = expf(lrelu(g_als1[n] + g_ald1[n] + g_ewmean*g_c1));
        g_selfc1[n] = es / (g_den1[n] + es);
    }
}

// K4: GAT2 GEMM (+als2/ald2); GCN2 scatter
__global__ __launch_bounds__(256) void k4(const int* eia, const float* bgat1, const float* Wa2,
                                          const float* asrc2, const float* adst2){
    __shared__ __align__(16) float xs[16*68];
    __shared__ float sred[32];
    int b = blockIdx.x, t = threadIdx.x;
    if (b < 64){
        int n0 = b*16;
        LdGAT ld{g_xd1, g_ha1, g_selfc1, bgat1};
        load_tile<64>(xs, n0, ld);
        int col = t & 63, rg = t >> 6;
        float acc[4];
        compute_tile<64>(xs, Wa2, col, rg, acc);
        #pragma unroll
        for (int i = 0; i < 4; i++) g_ha2[(n0 + rg*4 + i)*64 + col] = acc[i];
        attn_reduce(acc, asrc2, adst2, g_als2, g_ald2, n0, col, rg, sred);
    } else {
        scatter_w(eia, eia + EE, g_hg2, g_xa2, (b - 64)*64, true, 0, 0, 0, 0, 0.f, 0.f);
    }
}

// K5: GAT2 logits
__global__ __launch_bounds__(256) void k5(const int* eid, const float* ew){
    int e = blockIdx.x*256 + threadIdx.x;
    gat_logits(eid, eid + EE, ew, g_als2, g_ald2, g_c2, g_expE2, g_den2, e);
}

// K6: GAT2 aggregate; selfc2
__global__ __launch_bounds__(256) void k6(const int* eid){
    int b = blockIdx.x;
    if (b < 256){
        scatter_w(eid, eid + EE, g_ha2, g_xd2, b*64, false,
                  g_expE2, g_den2, g_als2, g_ald2, g_ewmean, g_c2);
    } else {
        int n = (b - 256)*256 + threadIdx.x;
        float es = expf(lrelu(g_als2[n] + g_ald2[n] + g_ewmean*g_c2));
        g_selfc2[n] = es / (g_den2[n] + es);
    }
}

// K7: combine xc = 0.7*xa2 + 0.3*xd2 and GCN3 GEMM
__global__ __launch_bounds__(256) void k7(const float* bg2, const float* bgat2, const float* Wg3){
    __shared__ __align__(16) float xs[16*68];
    int n0 = blockIdx.x*16;
    LdMix ld{bg2, bgat2};
    load_tile<64>(xs, n0, ld);
    int col = threadIdx.x & 63, rg = threadIdx.x >> 6;
    float acc[4];
    compute_tile<64>(xs, Wg3, col, rg, acc);
    #pragma unroll
    for (int i = 0; i < 4; i++) g_hg3[(n0 + rg*4 + i)*64 + col] = acc[i];
}

// K8: GCN3 scatter
__global__ __launch_bounds__(256) void k8(const int* eia){
    scatter_w(eia, eia + EE, g_hg3, g_h3, blockIdx.x*64, true, 0, 0, 0, 0, 0.f, 0.f);
}

// K9: final h -> h1p (with +bp1 folded), h2p
__global__ __launch_bounds__(256) void k9(const float* bg3, const float* Wp1, const float* bp1){
    __shared__ __align__(16) float xs[16*68];
    int n0 = blockIdx.x*16;
    LdGCN ld{g_h3, g_hg3, bg3};
    load_tile<64>(xs, n0, ld);
    int col = threadIdx.x & 63, rg = threadIdx.x >> 6;
    float acc[4];
    compute_tile<64>(xs, Wp1, col, rg, acc);
    float bb = bp1[col];
    #pragma unroll
    for (int i = 0; i < 4; i++) g_h1p[(n0 + rg*4 + i)*64 + col] = acc[i] + bb;
    compute_tile<64>(xs, Wp1 + 64*64, col, rg, acc);
    #pragma unroll
    for (int i = 0; i < 4; i++) g_h2p[(n0 + rg*4 + i)*64 + col] = acc[i];
}

// K10: all-pairs predictor. 64x64 output tile/block, 4x4 per thread.
__global__ __launch_bounds__(256) void k10(const float* Wp2, const float* bp2, float* out){
    __shared__ float s1[64*65];
    __shared__ float s2[64*65];
    __shared__ float swp[64];
    int bi = blockIdx.x >> 4, bj = blockIdx.x & 15;
    int i0 = bi*64, j0 = bj*64, t = threadIdx.x;
    for (int idx = t; idx < 4096; idx += 256){
        int nl = idx >> 6, h = idx & 63;
        s1[h*65 + nl] = g_h1p[(i0 + nl)*64 + h];
        s2[h*65 + nl] = g_h2p[(j0 + nl)*64 + h];
    }
    if (t < 64) swp[t] = Wp2[t];
    __syncthreads();
    int tx = t & 15, ty = t >> 4;
    float acc[4][4];
    #pragma unroll
    for (int a = 0; a < 4; a++)
        #pragma unroll
        for (int c = 0; c < 4; c++) acc[a][c] = 0.f;
    #pragma unroll 4
    for (int h = 0; h < 64; h++){
        float w = swp[h];
        float r1[4], r2[4];
        #pragma unroll
        for (int a = 0; a < 4; a++) r1[a] = s1[h*65 + a*16 + ty];
        #pragma unroll
        for (int c = 0; c < 4; c++) r2[c] = s2[h*65 + c*16 + tx];
        #pragma unroll
        for (int a = 0; a < 4; a++)
            #pragma unroll
            for (int c = 0; c < 4; c++)
                acc[a][c] += fmaxf(r1[a] + r2[c], 0.f) * w;
    }
    float bb = bp2[0];
    #pragma unroll
    for (int a = 0; a < 4; a++){
        int row = i0 + a*16 + ty;
        #pragma unroll
        for (int c = 0; c < 4; c++){
            float l = acc[a][c] + bb;
            out[row*1024 + j0 + c*16 + tx] = 1.0f / (1.0f + __expf(-l));
        }
    }
}

// ---------------- launch ----------------
extern "C" void kernel_launch(void* const* d_in, const int* in_sizes, int n_in,
                              void* d_out, int out_size){
    const float* x    = (const float*)d_in[0];
    const int*   eia  = (const int*)  d_in[1];
    const int*   eid  = (const int*)  d_in[2];
    const float* ew   = (const float*)d_in[3];
    const float* Wg1  = (const float*)d_in[4];
    const float* bg1  = (const float*)d_in[5];
    const float* Wa1  = (const float*)d_in[6];
    const float* as1  = (const float*)d_in[7];
    const float* ad1  = (const float*)d_in[8];
    const float* we1  = (const float*)d_in[9];
    const float* ae1  = (const float*)d_in[10];
    const float* bgat1= (const float*)d_in[11];
    const float* Wg2  = (const float*)d_in[12];
    const float* bg2  = (const float*)d_in[13];
    const float* Wa2  = (const float*)d_in[14];
    const float* as2  = (const float*)d_in[15];
    const float* ad2  = (const float*)d_in[16];
    const float* we2  = (const float*)d_in[17];
    const float* ae2  = (const float*)d_in[18];
    const float* bgat2= (const float*)d_in[19];
    const float* Wg3  = (const float*)d_in[20];
    const float* bg3  = (const float*)d_in[21];
    const float* Wp1  = (const float*)d_in[22];
    const float* bp1  = (const float*)d_in[23];
    const float* Wp2  = (const float*)d_in[24];
    const float* bp2  = (const float*)d_in[25];
    float* out = (float*)d_out;

    k0<<<257, 256>>>(ew, we1, ae1, we2, ae2);
    k1<<<128, 256>>>(x, eia, Wg1, Wa1, as1, ad1);
    k2<<<320, 256>>>(eia, eid, ew);
    k3<<<324, 256>>>(eid, bg1, Wg2);
    k4<<<320, 256>>>(eia, bgat1, Wa2, as2, ad2);
    k5<<<64, 256>>>(eid, ew);
    k6<<<260, 256>>>(eid);
    k7<<<64, 256>>>(bg2, bgat2, Wg3);
    k8<<<256, 256>>>(eia);
    k9<<<64, 256>>>(bg3, Wp1, bp1);
    k10<<<256, 256>>>(Wp2, bp2, out);
}

// round 2
// speedup vs baseline: 1.0918x; 1.0918x over previous
#include <cuda_runtime.h>
#include <cuda_bf16.h>

#define NN 1024
#define HH 64
#define EE 16384

// ---------------- scratch (device globals; no allocation) ----------------
__device__ __align__(16) float g_hg1[NN*HH], g_ha1[NN*HH], g_hg2[NN*HH], g_ha2[NN*HH], g_hg3[NN*HH];
__device__ __align__(16) float g_xa1[NN*HH], g_xd1[NN*HH], g_xa2[NN*HH], g_xd2[NN*HH], g_h3[NN*HH];
__device__ __align__(16) float g_h1p[NN*HH], g_h2pT[NN*HH];
__device__ float g_als1[NN], g_ald1[NN], g_als2[NN], g_ald2[NN];
__device__ float g_dinv[NN], g_selfe1[NN], g_selfe2[NN];
__device__ float g_expE1[EE], g_expE2[EE];
__device__ float g_ewmean, g_c1, g_c2;

// CSR structures (dst-sorted), rebuilt every launch
__device__ int g_part_a[16][NN], g_part_d[16][NN];
__device__ int g_off_a[NN+1], g_off_d[NN+1];
__device__ int g_tkt_a[NN], g_tkt_d[NN];
__device__ int g_src_a[EE];              // graph A: src per CSR slot
__device__ int g_src_d[EE], g_eid_d[EE]; // graph D: src + original edge id per slot

// ---------------- helpers ----------------
__device__ __forceinline__ float lrelu(float v){ return v > 0.f ? v : 0.2f*v; }

// tile GEMM: 16 nodes x 64 cols per block, 256 threads, thread = (col, rowgrp) -> 4 node-accums
template<int K, class L>
__device__ __forceinline__ void load_tile(float* xs, int n0, const L& ld){
    const int LD = K + 4;
    for (int idx = threadIdx.x; idx < 16*K; idx += 256){
        int ln = idx / K, k = idx - ln*K;
        xs[ln*LD + k] = ld(n0 + ln, k);
    }
    __syncthreads();
}

template<int K>
__device__ __forceinline__ void compute_tile(const float* xs, const float* __restrict__ W,
                                             int col, int rg, float acc[4]){
    const int LD = K + 4;
    const float* x0 = xs + rg*4*LD;
    acc[0]=0.f; acc[1]=0.f; acc[2]=0.f; acc[3]=0.f;
    #pragma unroll
    for (int k = 0; k < K; k += 4){
        float w0 = __ldg(W + (k+0)*64 + col);
        float w1 = __ldg(W + (k+1)*64 + col);
        float w2 = __ldg(W + (k+2)*64 + col);
        float w3 = __ldg(W + (k+3)*64 + col);
        #pragma unroll
        for (int i = 0; i < 4; i++){
            const float4 xv = *reinterpret_cast<const float4*>(x0 + i*LD + k);
            acc[i] = fmaf(xv.x, w0, acc[i]);
            acc[i] = fmaf(xv.y, w1, acc[i]);
            acc[i] = fmaf(xv.z, w2, acc[i]);
            acc[i] = fmaf(xv.w, w3, acc[i]);
        }
    }
}

// ---------------- loaders ----------------
struct LdRaw128 { const float* x;
    __device__ float operator()(int n, int k) const { return x[n*128 + k]; } };
struct LdRaw64 { const float* x;
    __device__ float operator()(int n, int k) const { return x[n*64 + k]; } };
struct LdMix {
    __device__ float operator()(int n, int k) const {
        return 0.7f*g_xa2[n*64+k] + 0.3f*g_xd2[n*64+k]; } };

// als/ald epilogue: reduce acc[i]*att over 64 cols
__device__ __forceinline__ void attn_reduce(const float acc[4], const float* asrc, const float* adst,
                                            float* outs, float* outd, int n0, int col, int rg,
                                            float* sred /*32 floats*/){
    int t = threadIdx.x;
    if (t < 32) sred[t] = 0.f;
    __syncthreads();
    float as = asrc[col], ad = adst[col];
    float ps[4], pd[4];
    #pragma unroll
    for (int i = 0; i < 4; i++){ ps[i] = acc[i]*as; pd[i] = acc[i]*ad; }
    #pragma unroll
    for (int off = 16; off > 0; off >>= 1){
        #pragma unroll
        for (int i = 0; i < 4; i++){
            ps[i] += __shfl_down_sync(0xffffffffu, ps[i], off);
            pd[i] += __shfl_down_sync(0xffffffffu, pd[i], off);
        }
    }
    if ((t & 31) == 0){
        #pragma unroll
        for (int i = 0; i < 4; i++){
            atomicAdd(&sred[rg*4 + i], ps[i]);
            atomicAdd(&sred[16 + rg*4 + i], pd[i]);
        }
    }
    __syncthreads();
    if (t < 16){ outs[n0+t] = sred[t]; outd[n0+t] = sred[16+t]; }
}

// ---------------- gathers (CSR, no atomics) ----------------
// GCN: out[d,col] = relu( dinv[d]*sum_in(dinv[s]*h[s,col]) + dinv[d]^2*h[d,col] + bias[col] )
__device__ __forceinline__ void gather_gcn(const float* __restrict__ h, const float* __restrict__ bias,
                                           float* __restrict__ out, int nodeBase){
    int t = threadIdx.x;
    int node = nodeBase + (t >> 6);
    int col = t & 63;
    int beg = g_off_a[node], end = g_off_a[node+1];
    float acc = 0.f;
    int i = beg;
    for (; i + 4 <= end; i += 4){
        int s0 = g_src_a[i+0], s1 = g_src_a[i+1], s2 = g_src_a[i+2], s3 = g_src_a[i+3];
        float v0 = g_dinv[s0]*h[s0*64+col];
        float v1 = g_dinv[s1]*h[s1*64+col];
        float v2 = g_dinv[s2]*h[s2*64+col];
        float v3 = g_dinv[s3]*h[s3*64+col];
        acc += (v0+v1)+(v2+v3);
    }
    for (; i < end; i++){ int s = g_src_a[i]; acc += g_dinv[s]*h[s*64+col]; }
    float dd = g_dinv[node];
    float o = dd*acc + dd*dd*h[node*64+col] + bias[col];
    out[node*64+col] = fmaxf(o, 0.f);
}

// GAT: out[d,col] = relu( (sum_in exp_e*h[s,col] + selfe*h[d,col]) / (sum_in exp_e + selfe) + bias[col] )
__device__ __forceinline__ void gather_gat(const float* __restrict__ h, const float* __restrict__ expE,
                                           const float* __restrict__ selfe, const float* __restrict__ bias,
                                           float* __restrict__ out, int nodeBase){
    int t = threadIdx.x;
    int node = nodeBase + (t >> 6);
    int col = t & 63;
    int beg = g_off_d[node], end = g_off_d[node+1];
    float acc = 0.f, den = 0.f;
    int i = beg;
    for (; i + 4 <= end; i += 4){
        int s0 = g_src_d[i+0], s1 = g_src_d[i+1], s2 = g_src_d[i+2], s3 = g_src_d[i+3];
        float x0 = expE[g_eid_d[i+0]], x1 = expE[g_eid_d[i+1]];
        float x2 = expE[g_eid_d[i+2]], x3 = expE[g_eid_d[i+3]];
        den += (x0+x1)+(x2+x3);
        acc = fmaf(x0, h[s0*64+col], acc);
        acc = fmaf(x1, h[s1*64+col], acc);
        acc = fmaf(x2, h[s2*64+col], acc);
        acc = fmaf(x3, h[s3*64+col], acc);
    }
    for (; i < end; i++){
        int s = g_src_d[i]; float x = expE[g_eid_d[i]];
        den += x; acc = fmaf(x, h[s*64+col], acc);
    }
    float es = selfe[node];
    float o = (acc + es*h[node*64+col]) / (den + es) + bias[col];
    out[node*64+col] = fmaxf(o, 0.f);
}

// ---------------- K0: GEMM1 + hist partials + scalars ----------------
__global__ __launch_bounds__(256) void k0(const float* __restrict__ x,
                                          const int* __restrict__ eia, const int* __restrict__ eid,
                                          const float* __restrict__ ew,
                                          const float* __restrict__ Wg, const float* __restrict__ Wa,
                                          const float* __restrict__ asrc, const float* __restrict__ adst,
                                          const float* __restrict__ we1, const float* __restrict__ ae1,
                                          const float* __restrict__ we2, const float* __restrict__ ae2){
    int b = blockIdx.x, t = threadIdx.x;
    if (b < 64){
        __shared__ __align__(16) float xs[16*132];
        __shared__ float sred[32];
        int n0 = b*16;
        LdRaw128 ld{x};
        load_tile<128>(xs, n0, ld);
        int col = t & 63, rg = t >> 6;
        float acc[4];
        compute_tile<128>(xs, Wg, col, rg, acc);
        #pragma unroll
        for (int i = 0; i < 4; i++) g_hg1[(n0 + rg*4 + i)*64 + col] = acc[i];
        compute_tile<128>(xs, Wa, col, rg, acc);
        #pragma unroll
        for (int i = 0; i < 4; i++) g_ha1[(n0 + rg*4 + i)*64 + col] = acc[i];
        attn_reduce(acc, asrc, adst, g_als1, g_ald1, n0, col, rg, sred);
    } else if (b < 96){
        // histogram partials: 16 blocks per graph, 1024 edges each
        __shared__ int hc[NN];
        int g = (b - 64) >> 4;           // 0 = graph A, 1 = graph D
        int bb = (b - 64) & 15;
        const int* dst = (g == 0) ? (eia + EE) : (eid + EE);
        int (*part)[NN] = (g == 0) ? g_part_a : g_part_d;
        #pragma unroll
        for (int i = t; i < NN; i += 256) hc[i] = 0;
        __syncthreads();
        int e0 = bb*1024;
        #pragma unroll
        for (int it = 0; it < 4; it++) atomicAdd(&hc[dst[e0 + it*256 + t]], 1);
        __syncthreads();
        #pragma unroll
        for (int i = t; i < NN; i += 256) part[bb][i] = hc[i];
    } else {
        // scalars: ewmean, c1, c2
        __shared__ float sr[256];
        float s = 0.f;
        for (int i = t; i < EE; i += 256) s += ew[i];
        sr[t] = s; __syncthreads();
        for (int o = 128; o > 0; o >>= 1){ if (t < o) sr[t] += sr[t+o]; __syncthreads(); }
        if (t == 0) g_ewmean = sr[0] * (1.0f/EE);
        __syncthreads();
        sr[t] = (t < 64) ? we1[t]*ae1[t] : 0.f; __syncthreads();
        for (int o = 128; o > 0; o >>= 1){ if (t < o) sr[t] += sr[t+o]; __syncthreads(); }
        if (t == 0) g_c1 = sr[0];
        __syncthreads();
        sr[t] = (t < 64) ? we2[t]*ae2[t] : 0.f; __syncthreads();
        for (int o = 128; o > 0; o >>= 1){ if (t < o) sr[t] += sr[t+o]; __syncthreads(); }
        if (t == 0) g_c2 = sr[0];
    }
}

// ---------------- K1: scan (both graphs) + expE1 + selfe1 ----------------
__global__ __launch_bounds__(256) void k1(const int* __restrict__ eid, const float* __restrict__ ew){
    int b = blockIdx.x, t = threadIdx.x;
    if (b < 2){
        const int (*part)[NN] = (b == 0) ? g_part_a : g_part_d;
        int* off = (b == 0) ? g_off_a : g_off_d;
        int* tkt = (b == 0) ? g_tkt_a : g_tkt_d;
        __shared__ int ts[256];
        int base = t*4;
        int v0=0, v1=0, v2=0, v3=0;
        #pragma unroll
        for (int p = 0; p < 16; p++){
            const int4 q = *reinterpret_cast<const int4*>(&part[p][base]);
            v0 += q.x; v1 += q.y; v2 += q.z; v3 += q.w;
        }
        int local = v0+v1+v2+v3;
        ts[t] = local; __syncthreads();
        for (int o = 1; o < 256; o <<= 1){
            int add = (t >= o) ? ts[t-o] : 0;
            __syncthreads();
            ts[t] += add;
            __syncthreads();
        }
        int excl = ts[t] - local;
        int o0 = excl, o1 = o0+v0, o2 = o1+v1, o3 = o2+v2;
        off[base]=o0; off[base+1]=o1; off[base+2]=o2; off[base+3]=o3;
        tkt[base]=o0; tkt[base+1]=o1; tkt[base+2]=o2; tkt[base+3]=o3;
        if (t == 255) off[NN] = o3 + v3;
        if (b == 0){
            g_dinv[base+0] = rsqrtf((float)(v0+1));
            g_dinv[base+1] = rsqrtf((float)(v1+1));
            g_dinv[base+2] = rsqrtf((float)(v2+1));
            g_dinv[base+3] = rsqrtf((float)(v3+1));
        }
    } else if (b < 66){
        int e = (b-2)*256 + t;
        int s = eid[e], d = eid[EE + e];
        g_expE1[e] = __expf(lrelu(g_als1[s] + g_ald1[d] + ew[e]*g_c1));
    } else {
        int n = (b-66)*256 + t;
        g_selfe1[n] = __expf(lrelu(g_als1[n] + g_ald1[n] + g_ewmean*g_c1));
    }
}

// ---------------- K2: CSR fill (both graphs) ----------------
__global__ __launch_bounds__(256) void k2(const int* __restrict__ eia, const int* __restrict__ eid){
    int b = blockIdx.x, t = threadIdx.x;
    if (b < 64){
        int e = b*256 + t;
        int d = eia[EE + e];
        int pos = atomicAdd(&g_tkt_a[d], 1);
        g_src_a[pos] = eia[e];
    } else {
        int e = (b-64)*256 + t;
        int d = eid[EE + e];
        int pos = atomicAdd(&g_tkt_d[d], 1);
        g_src_d[pos] = eid[e];
        g_eid_d[pos] = e;
    }
}

// ---------------- K3: GCN1 gather + GAT1 gather ----------------
__global__ __launch_bounds__(256) void k3(const float* __restrict__ bg1, const float* __restrict__ bgat1){
    int b = blockIdx.x;
    if (b < 256) gather_gcn(g_hg1, bg1, g_xa1, b*4);
    else         gather_gat(g_ha1, g_expE1, g_selfe1, bgat1, g_xd1, (b-256)*4);
}

// ---------------- K4: GCN2 GEMM + GAT2 GEMM (+attn2) ----------------
__global__ __launch_bounds__(256) void k4(const float* __restrict__ Wg2, const float* __restrict__ Wa2,
                                          const float* __restrict__ as2, const float* __restrict__ ad2){
    __shared__ __align__(16) float xs[16*68];
    __shared__ float sred[32];
    int b = blockIdx.x, t = threadIdx.x;
    int col = t & 63, rg = t >> 6;
    float acc[4];
    if (b < 64){
        int n0 = b*16;
        LdRaw64 ld{g_xa1};
        load_tile<64>(xs, n0, ld);
        compute_tile<64>(xs, Wg2, col, rg, acc);
        #pragma unroll
        for (int i = 0; i < 4; i++) g_hg2[(n0 + rg*4 + i)*64 + col] = acc[i];
    } else {
        int n0 = (b-64)*16;
        LdRaw64 ld{g_xd1};
        load_tile<64>(xs, n0, ld);
        compute_tile<64>(xs, Wa2, col, rg, acc);
        #pragma unroll
        for (int i = 0; i < 4; i++) g_ha2[(n0 + rg*4 + i)*64 + col] = acc[i];
        attn_reduce(acc, as2, ad2, g_als2, g_ald2, n0, col, rg, sred);
    }
}

// ---------------- K5: GCN2 gather + expE2 + selfe2 ----------------
__global__ __launch_bounds__(256) void k5(const float* __restrict__ bg2,
                                          const int* __restrict__ eid, const float* __restrict__ ew){
    int b = blockIdx.x, t = threadIdx.x;
    if (b < 256){
        gather_gcn(g_hg2, bg2, g_xa2, b*4);
    } else if (b < 320){
        int e = (b-256)*256 + t;
        int s = eid[e], d = eid[EE + e];
        g_expE2[e] = __expf(lrelu(g_als2[s] + g_ald2[d] + ew[e]*g_c2));
    } else {
        int n = (b-320)*256 + t;
        g_selfe2[n] = __expf(lrelu(g_als2[n] + g_ald2[n] + g_ewmean*g_c2));
    }
}

// ---------------- K6: GAT2 gather ----------------
__global__ __launch_bounds__(256) void k6(const float* __restrict__ bgat2){
    gather_gat(g_ha2, g_expE2, g_selfe2, bgat2, g_xd2, blockIdx.x*4);
}

// ---------------- K7: combine + GCN3 GEMM ----------------
__global__ __launch_bounds__(256) void k7(const float* __restrict__ Wg3){
    __shared__ __align__(16) float xs[16*68];
    int n0 = blockIdx.x*16;
    LdMix ld{};
    load_tile<64>(xs, n0, ld);
    int col = threadIdx.x & 63, rg = threadIdx.x >> 6;
    float acc[4];
    compute_tile<64>(xs, Wg3, col, rg, acc);
    #pragma unroll
    for (int i = 0; i < 4; i++) g_hg3[(n0 + rg*4 + i)*64 + col] = acc[i];
}

// ---------------- K8: GCN3 gather ----------------
__global__ __launch_bounds__(256) void k8(const float* __restrict__ bg3){
    gather_gcn(g_hg3, bg3, g_h3, blockIdx.x*4);
}

// ---------------- K9: predictor GEMM: h1p (+bp1), h2pT (transposed) ----------------
__global__ __launch_bounds__(256) void k9(const float* __restrict__ Wp1, const float* __restrict__ bp1){
    __shared__ __align__(16) float xs[16*68];
    int n0 = blockIdx.x*16;
    LdRaw64 ld{g_h3};
    load_tile<64>(xs, n0, ld);
    int col = threadIdx.x & 63, rg = threadIdx.x >> 6;
    float acc[4];
    compute_tile<64>(xs, Wp1, col, rg, acc);
    float bb = bp1[col];
    #pragma unroll
    for (int i = 0; i < 4; i++) g_h1p[(n0 + rg*4 + i)*64 + col] = acc[i] + bb;
    compute_tile<64>(xs, Wp1 + 64*64, col, rg, acc);
    // transposed store: h2pT[col*1024 + node], 4 consecutive nodes -> float4
    float4 o; o.x = acc[0]; o.y = acc[1]; o.z = acc[2]; o.w = acc[3];
    *reinterpret_cast<float4*>(g_h2pT + col*NN + n0 + rg*4) = o;
}

// ---------------- K10: all-pairs predictor (64x64 tile, 4x4/thread) ----------------
__global__ __launch_bounds__(256) void k10(const float* __restrict__ Wp2, const float* __restrict__ bp2,
                                           float* __restrict__ out){
    __shared__ __align__(16) float s1[4096];   // node-major: s1[nl*64 + h]
    __shared__ __align__(16) float s2[4096];   // h-major:    s2[h*64 + nl]
    __shared__ float swp[64];
    int bi = blockIdx.x >> 4, bj = blockIdx.x & 15;
    int i0 = bi*64, j0 = bj*64, t = threadIdx.x;
    {   // s1: copy rows (already node-major) — perfectly coalesced float4
        int row = t >> 2, hb = (t & 3)*16;
        const float4* src = reinterpret_cast<const float4*>(g_h1p + (i0+row)*64 + hb);
        float4* dst = reinterpret_cast<float4*>(s1 + row*64 + hb);
        dst[0]=src[0]; dst[1]=src[1]; dst[2]=src[2]; dst[3]=src[3];
    }
    {   // s2: h-major rows come from pre-transposed h2pT
        int h = t >> 2, nb = (t & 3)*16;
        const float4* src = reinterpret_cast<const float4*>(g_h2pT + h*NN + j0 + nb);
        float4* dst = reinterpret_cast<float4*>(s2 + h*64 + nb);
        dst[0]=src[0]; dst[1]=src[1]; dst[2]=src[2]; dst[3]=src[3];
    }
    if (t < 64) swp[t] = Wp2[t];
    __syncthreads();

    int tx = t & 15, ty = t >> 4;
    const float* p1 = s1 + ty*4*64;
    const float* p2 = s2 + tx*4;
    float acc[4][4];
    #pragma unroll
    for (int a = 0; a < 4; a++)
        #pragma unroll
        for (int c = 0; c < 4; c++) acc[a][c] = 0.f;

    #pragma unroll 4
    for (int h = 0; h < 64; h++){
        float w = swp[h];
        float4 r2 = *reinterpret_cast<const float4*>(p2 + h*64);
        float r1a = p1[h], r1b = p1[64 + h], r1c = p1[128 + h], r1d = p1[192 + h];
        acc[0][0] = fmaf(fmaxf(r1a + r2.x, 0.f), w, acc[0][0]);
        acc[0][1] = fmaf(fmaxf(r1a + r2.y, 0.f), w, acc[0][1]);
        acc[0][2] = fmaf(fmaxf(r1a + r2.z, 0.f), w, acc[0][2]);
        acc[0][3] = fmaf(fmaxf(r1a + r2.w, 0.f), w, acc[0][3]);
        acc[1][0] = fmaf(fmaxf(r1b + r2.x, 0.f), w, acc[1][0]);
        acc[1][1] = fmaf(fmaxf(r1b + r2.y, 0.f), w, acc[1][1]);
        acc[1][2] = fmaf(fmaxf(r1b + r2.z, 0.f), w, acc[1][2]);
        acc[1][3] = fmaf(fmaxf(r1b + r2.w, 0.f), w, acc[1][3]);
        acc[2][0] = fmaf(fmaxf(r1c + r2.x, 0.f), w, acc[2][0]);
        acc[2][1] = fmaf(fmaxf(r1c + r2.y, 0.f), w, acc[2][1]);
        acc[2][2] = fmaf(fmaxf(r1c + r2.z, 0.f), w, acc[2][2]);
        acc[2][3] = fmaf(fmaxf(r1c + r2.w, 0.f), w, acc[2][3]);
        acc[3][0] = fmaf(fmaxf(r1d + r2.x, 0.f), w, acc[3][0]);
        acc[3][1] = fmaf(fmaxf(r1d + r2.y, 0.f), w, acc[3][1]);
        acc[3][2] = fmaf(fmaxf(r1d + r2.z, 0.f), w, acc[3][2]);
        acc[3][3] = fmaf(fmaxf(r1d + r2.w, 0.f), w, acc[3][3]);
    }
    float bb = bp2[0];
    #pragma unroll
    for (int a = 0; a < 4; a++){
        int row = i0 + ty*4 + a;
        float4 o;
        o.x = 1.0f / (1.0f + __expf(-(acc[a][0] + bb)));
        o.y = 1.0f / (1.0f + __expf(-(acc[a][1] + bb)));
        o.z = 1.0f / (1.0f + __expf(-(acc[a][2] + bb)));
        o.w = 1.0f / (1.0f + __expf(-(acc[a][3] + bb)));
        *reinterpret_cast<float4*>(out + row*NN + j0 + tx*4) = o;
    }
}

// ---------------- launch ----------------
extern "C" void kernel_launch(void* const* d_in, const int* in_sizes, int n_in,
                              void* d_out, int out_size){
    const float* x    = (const float*)d_in[0];
    const int*   eia  = (const int*)  d_in[1];
    const int*   eid  = (const int*)  d_in[2];
    const float* ew   = (const float*)d_in[3];
    const float* Wg1  = (const float*)d_in[4];
    const float* bg1  = (const float*)d_in[5];
    const float* Wa1  = (const float*)d_in[6];
    const float* as1  = (const float*)d_in[7];
    const float* ad1  = (const float*)d_in[8];
    const float* we1  = (const float*)d_in[9];
    const float* ae1  = (const float*)d_in[10];
    const float* bgat1= (const float*)d_in[11];
    const float* Wg2  = (const float*)d_in[12];
    const float* bg2  = (const float*)d_in[13];
    const float* Wa2  = (const float*)d_in[14];
    const float* as2  = (const float*)d_in[15];
    const float* ad2  = (const float*)d_in[16];
    const float* we2  = (const float*)d_in[17];
    const float* ae2  = (const float*)d_in[18];
    const float* bgat2= (const float*)d_in[19];
    const float* Wg3  = (const float*)d_in[20];
    const float* bg3  = (const float*)d_in[21];
    const float* Wp1  = (const float*)d_in[22];
    const float* bp1  = (const float*)d_in[23];
    const float* Wp2  = (const float*)d_in[24];
    const float* bp2  = (const float*)d_in[25];
    float* out = (float*)d_out;

    k0<<<97, 256>>>(x, eia, eid, ew, Wg1, Wa1, as1, ad1, we1, ae1, we2, ae2);
    k1<<<70, 256>>>(eid, ew);
    k2<<<128, 256>>>(eia, eid);
    k3<<<512, 256>>>(bg1, bgat1);
    k4<<<128, 256>>>(Wg2, Wa2, as2, ad2);
    k5<<<324, 256>>>(bg2, eid, ew);
    k6<<<256, 256>>>(bgat2);
    k7<<<64, 256>>>(Wg3);
    k8<<<256, 256>>>(bg3);
    k9<<<64, 256>>>(Wp1, bp1);
    k10<<<256, 256>>>(Wp2, bp2, out);
}

// round 3
// speedup vs baseline: 1.3041x; 1.1944x over previous
#include <cuda_runtime.h>
#include <cuda_bf16.h>

#define NN 1024
#define HH 64
#define EE 16384

typedef unsigned long long ull;

// ---------------- scratch (device globals; no allocation) ----------------
__device__ __align__(16) float g_hg1[NN*HH], g_ha1[NN*HH], g_hg2[NN*HH], g_ha2[NN*HH], g_hg3[NN*HH];
__device__ __align__(16) float g_xa1[NN*HH], g_xd1[NN*HH], g_xa2[NN*HH], g_xd2[NN*HH], g_h3[NN*HH];
__device__ __align__(16) float g_h1p[NN*HH], g_h2pT[NN*HH];
__device__ float g_als1[NN], g_ald1[NN], g_als2[NN], g_ald2[NN];
__device__ float g_dinv[NN], g_selfe1[NN], g_selfe2[NN];
__device__ float g_rs1[NN], g_rs2[NN];
__device__ float g_ewmean, g_c1, g_c2;

// CSR (dst-sorted), rebuilt each launch
__device__ int g_part_a[16][NN], g_part_d[16][NN];
__device__ int g_off_a[NN+1], g_off_d[NN+1];
__device__ int g_tkt_a[NN], g_tkt_d[NN];
__device__ __align__(8) float2 g_pk_a[EE];      // (dinv[s], src)
__device__ __align__(8) float2 g_pk_d1[EE];     // (expE1, src)
__device__ __align__(8) float2 g_pk_d2[EE];     // (expE2, src)
__device__ int g_dst_d[EE];
__device__ float g_ewp[EE];

// ---------------- helpers ----------------
__device__ __forceinline__ float lrelu(float v){ return v > 0.f ? v : 0.2f*v; }

__device__ __forceinline__ ull f2add(ull a, ull b){
    ull r; asm("add.rn.f32x2 %0, %1, %2;" : "=l"(r) : "l"(a), "l"(b)); return r;
}
__device__ __forceinline__ ull f2fma(ull a, ull b, ull c){
    ull r; asm("fma.rn.f32x2 %0, %1, %2, %3;" : "=l"(r) : "l"(a), "l"(b), "l"(c)); return r;
}
__device__ __forceinline__ float f2lo(ull v){ return __uint_as_float((unsigned)v); }
__device__ __forceinline__ float f2hi(ull v){ return __uint_as_float((unsigned)(v >> 32)); }
__device__ __forceinline__ ull fdup(float f){ ull u = __float_as_uint(f); return u | (u << 32); }

// ---------------- 8-node GEMM tiles (256 thr: col=t&63, rg=t>>6 -> 2 rows) ----------------
template<int K, class L>
__device__ __forceinline__ void load_tile8(float* xs, int n0, const L& ld){
    const int LD = K + 4;
    for (int idx = threadIdx.x; idx < 8*K; idx += 256){
        int ln = idx / K, k = idx - ln*K;
        xs[ln*LD + k] = ld(n0 + ln, k);
    }
    __syncthreads();
}

template<int K>
__device__ __forceinline__ void compute_tile8(const float* xs, const float* __restrict__ W,
                                              int col, int rg, float acc[2]){
    const int LD = K + 4;
    const float* x0 = xs + rg*2*LD;
    acc[0]=0.f; acc[1]=0.f;
    #pragma unroll
    for (int k = 0; k < K; k += 4){
        float w0 = __ldg(W + (k+0)*64 + col);
        float w1 = __ldg(W + (k+1)*64 + col);
        float w2 = __ldg(W + (k+2)*64 + col);
        float w3 = __ldg(W + (k+3)*64 + col);
        #pragma unroll
        for (int i = 0; i < 2; i++){
            const float4 xv = *reinterpret_cast<const float4*>(x0 + i*LD + k);
            acc[i] = fmaf(xv.x, w0, acc[i]);
            acc[i] = fmaf(xv.y, w1, acc[i]);
            acc[i] = fmaf(xv.z, w2, acc[i]);
            acc[i] = fmaf(xv.w, w3, acc[i]);
        }
    }
}

struct LdRaw128 { const float* x;
    __device__ float operator()(int n, int k) const { return x[n*128 + k]; } };
struct LdRaw64 { const float* x;
    __device__ float operator()(int n, int k) const { return x[n*64 + k]; } };
struct LdMix {
    __device__ float operator()(int n, int k) const {
        return 0.7f*g_xa2[n*64+k] + 0.3f*g_xd2[n*64+k]; } };

// dual weighted column-reduction over 8-node tile: outA[n]=sum_col aA*wA, outB likewise
__device__ __forceinline__ void attn_reduce8(float aA0, float aA1, float aB0, float aB1,
                                             float wA, float wB,
                                             float* outA, float* outB, int n0, int rg, float* sred){
    int t = threadIdx.x;
    if (t < 16) sred[t] = 0.f;
    __syncthreads();
    float p0 = aA0*wA, p1 = aA1*wA, q0 = aB0*wB, q1 = aB1*wB;
    #pragma unroll
    for (int off = 16; off > 0; off >>= 1){
        p0 += __shfl_down_sync(0xffffffffu, p0, off);
        p1 += __shfl_down_sync(0xffffffffu, p1, off);
        q0 += __shfl_down_sync(0xffffffffu, q0, off);
        q1 += __shfl_down_sync(0xffffffffu, q1, off);
    }
    if ((t & 31) == 0){
        atomicAdd(&sred[rg*2+0], p0);
        atomicAdd(&sred[rg*2+1], p1);
        atomicAdd(&sred[8+rg*2+0], q0);
        atomicAdd(&sred[8+rg*2+1], q1);
    }
    __syncthreads();
    if (t < 8){ outA[n0+t] = sred[t]; outB[n0+t] = sred[8+t]; }
}

// ---------------- gathers: warp per node; lane = part*16 + col4 ----------------
__device__ __forceinline__ void gather_gcn(const float* __restrict__ h, const float* __restrict__ bias,
                                           float* __restrict__ out, int node){
    int lane = threadIdx.x & 31;
    int col4 = lane & 15, part = lane >> 4;
    const float2* __restrict__ pk = g_pk_a;
    int beg = g_off_a[node], end = g_off_a[node+1];
    float4 acc = make_float4(0.f,0.f,0.f,0.f);
    int i = beg + part;
    for (; i + 6 < end; i += 8){
        float2 q0 = __ldg(pk+i),   q1 = __ldg(pk+i+2);
        float2 q2 = __ldg(pk+i+4), q3 = __ldg(pk+i+6);
        int s0=__float_as_int(q0.y), s1=__float_as_int(q1.y);
        int s2=__float_as_int(q2.y), s3=__float_as_int(q3.y);
        float4 h0 = *(const float4*)(h + s0*64 + col4*4);
        float4 h1 = *(const float4*)(h + s1*64 + col4*4);
        float4 h2 = *(const float4*)(h + s2*64 + col4*4);
        float4 h3 = *(const float4*)(h + s3*64 + col4*4);
        acc.x = fmaf(q0.x,h0.x, fmaf(q1.x,h1.x, fmaf(q2.x,h2.x, fmaf(q3.x,h3.x, acc.x))));
        acc.y = fmaf(q0.x,h0.y, fmaf(q1.x,h1.y, fmaf(q2.x,h2.y, fmaf(q3.x,h3.y, acc.y))));
        acc.z = fmaf(q0.x,h0.z, fmaf(q1.x,h1.z, fmaf(q2.x,h2.z, fmaf(q3.x,h3.z, acc.z))));
        acc.w = fmaf(q0.x,h0.w, fmaf(q1.x,h1.w, fmaf(q2.x,h2.w, fmaf(q3.x,h3.w, acc.w))));
    }
    for (; i < end; i += 2){
        float2 q = __ldg(pk+i);
        int s = __float_as_int(q.y);
        float4 hv = *(const float4*)(h + s*64 + col4*4);
        acc.x = fmaf(q.x,hv.x,acc.x); acc.y = fmaf(q.x,hv.y,acc.y);
        acc.z = fmaf(q.x,hv.z,acc.z); acc.w = fmaf(q.x,hv.w,acc.w);
    }
    acc.x += __shfl_xor_sync(0xffffffffu, acc.x, 16);
    acc.y += __shfl_xor_sync(0xffffffffu, acc.y, 16);
    acc.z += __shfl_xor_sync(0xffffffffu, acc.z, 16);
    acc.w += __shfl_xor_sync(0xffffffffu, acc.w, 16);
    if (part == 0){
        float dd = g_dinv[node];
        float4 hs = *(const float4*)(h + node*64 + col4*4);
        float4 bb = *(const float4*)(bias + col4*4);
        float4 o;
        o.x = fmaxf(fmaf(dd, fmaf(dd, hs.x, acc.x), bb.x), 0.f);
        o.y = fmaxf(fmaf(dd, fmaf(dd, hs.y, acc.y), bb.y), 0.f);
        o.z = fmaxf(fmaf(dd, fmaf(dd, hs.z, acc.z), bb.z), 0.f);
        o.w = fmaxf(fmaf(dd, fmaf(dd, hs.w, acc.w), bb.w), 0.f);
        *(float4*)(out + node*64 + col4*4) = o;
    }
}

__device__ __forceinline__ void gather_gat(const float* __restrict__ h, const float2* __restrict__ pk,
                                           const float* __restrict__ selfe, const float* __restrict__ bias,
                                           float* __restrict__ out, int node){
    int lane = threadIdx.x & 31;
    int col4 = lane & 15, part = lane >> 4;
    int beg = g_off_d[node], end = g_off_d[node+1];
    float4 acc = make_float4(0.f,0.f,0.f,0.f);
    float den = 0.f;
    int i = beg + part;
    for (; i + 6 < end; i += 8){
        float2 q0 = __ldg(pk+i),   q1 = __ldg(pk+i+2);
        float2 q2 = __ldg(pk+i+4), q3 = __ldg(pk+i+6);
        int s0=__float_as_int(q0.y), s1=__float_as_int(q1.y);
        int s2=__float_as_int(q2.y), s3=__float_as_int(q3.y);
        float4 h0 = *(const float4*)(h + s0*64 + col4*4);
        float4 h1 = *(const float4*)(h + s1*64 + col4*4);
        float4 h2 = *(const float4*)(h + s2*64 + col4*4);
        float4 h3 = *(const float4*)(h + s3*64 + col4*4);
        den += (q0.x+q1.x)+(q2.x+q3.x);
        acc.x = fmaf(q0.x,h0.x, fmaf(q1.x,h1.x, fmaf(q2.x,h2.x, fmaf(q3.x,h3.x, acc.x))));
        acc.y = fmaf(q0.x,h0.y, fmaf(q1.x,h1.y, fmaf(q2.x,h2.y, fmaf(q3.x,h3.y, acc.y))));
        acc.z = fmaf(q0.x,h0.z, fmaf(q1.x,h1.z, fmaf(q2.x,h2.z, fmaf(q3.x,h3.z, acc.z))));
        acc.w = fmaf(q0.x,h0.w, fmaf(q1.x,h1.w, fmaf(q2.x,h2.w, fmaf(q3.x,h3.w, acc.w))));
    }
    for (; i < end; i += 2){
        float2 q = __ldg(pk+i);
        int s = __float_as_int(q.y);
        float4 hv = *(const float4*)(h + s*64 + col4*4);
        den += q.x;
        acc.x = fmaf(q.x,hv.x,acc.x); acc.y = fmaf(q.x,hv.y,acc.y);
        acc.z = fmaf(q.x,hv.z,acc.z); acc.w = fmaf(q.x,hv.w,acc.w);
    }
    acc.x += __shfl_xor_sync(0xffffffffu, acc.x, 16);
    acc.y += __shfl_xor_sync(0xffffffffu, acc.y, 16);
    acc.z += __shfl_xor_sync(0xffffffffu, acc.z, 16);
    acc.w += __shfl_xor_sync(0xffffffffu, acc.w, 16);
    den   += __shfl_xor_sync(0xffffffffu, den, 16);
    if (part == 0){
        float es = selfe[node];
        float inv = 1.0f / (den + es);
        float4 hs = *(const float4*)(h + node*64 + col4*4);
        float4 bb = *(const float4*)(bias + col4*4);
        float4 o;
        o.x = fmaxf(fmaf(es, hs.x, acc.x)*inv + bb.x, 0.f);
        o.y = fmaxf(fmaf(es, hs.y, acc.y)*inv + bb.y, 0.f);
        o.z = fmaxf(fmaf(es, hs.z, acc.z)*inv + bb.z, 0.f);
        o.w = fmaxf(fmaf(es, hs.w, acc.w)*inv + bb.w, 0.f);
        *(float4*)(out + node*64 + col4*4) = o;
    }
}

// ---------------- K0: GEMM1 (128 blocks) + hist (32) + scalars (1) ----------------
__global__ __launch_bounds__(256) void k0(const float* __restrict__ x,
                                          const int* __restrict__ eia, const int* __restrict__ eid,
                                          const float* __restrict__ ew,
                                          const float* __restrict__ Wg, const float* __restrict__ Wa,
                                          const float* __restrict__ asrc, const float* __restrict__ adst,
                                          const float* __restrict__ we1, const float* __restrict__ ae1,
                                          const float* __restrict__ we2, const float* __restrict__ ae2){
    int b = blockIdx.x, t = threadIdx.x;
    if (b < 128){
        __shared__ __align__(16) float xs[8*132];
        __shared__ float sred[16];
        int n0 = b*8;
        LdRaw128 ld{x};
        load_tile8<128>(xs, n0, ld);
        int col = t & 63, rg = t >> 6;
        float acc[2];
        compute_tile8<128>(xs, Wg, col, rg, acc);
        #pragma unroll
        for (int i = 0; i < 2; i++) g_hg1[(n0 + rg*2 + i)*64 + col] = acc[i];
        compute_tile8<128>(xs, Wa, col, rg, acc);
        #pragma unroll
        for (int i = 0; i < 2; i++) g_ha1[(n0 + rg*2 + i)*64 + col] = acc[i];
        attn_reduce8(acc[0], acc[1], acc[0], acc[1], asrc[col], adst[col],
                     g_als1, g_ald1, n0, rg, sred);
    } else if (b < 160){
        __shared__ int hc[NN];
        int g = (b - 128) >> 4;
        int bb = (b - 128) & 15;
        const int* dst = (g == 0) ? (eia + EE) : (eid + EE);
        int (*part)[NN] = (g == 0) ? g_part_a : g_part_d;
        for (int i = t; i < NN; i += 256) hc[i] = 0;
        __syncthreads();
        int e0 = bb*1024;
        #pragma unroll
        for (int it = 0; it < 4; it++) atomicAdd(&hc[dst[e0 + it*256 + t]], 1);
        __syncthreads();
        for (int i = t; i < NN; i += 256) part[bb][i] = hc[i];
    } else {
        __shared__ float sr[256];
        float s = 0.f;
        for (int i = t; i < EE; i += 256) s += ew[i];
        sr[t] = s; __syncthreads();
        for (int o = 128; o > 0; o >>= 1){ if (t < o) sr[t] += sr[t+o]; __syncthreads(); }
        if (t == 0) g_ewmean = sr[0] * (1.0f/EE);
        __syncthreads();
        sr[t] = (t < 64) ? we1[t]*ae1[t] : 0.f; __syncthreads();
        for (int o = 128; o > 0; o >>= 1){ if (t < o) sr[t] += sr[t+o]; __syncthreads(); }
        if (t == 0) g_c1 = sr[0];
        __syncthreads();
        sr[t] = (t < 64) ? we2[t]*ae2[t] : 0.f; __syncthreads();
        for (int o = 128; o > 0; o >>= 1){ if (t < o) sr[t] += sr[t+o]; __syncthreads(); }
        if (t == 0) g_c2 = sr[0];
    }
}

// ---------------- K1: scan (2 blocks) + selfe1 (4 blocks) ----------------
__global__ __launch_bounds__(256) void k1(void){
    int b = blockIdx.x, t = threadIdx.x;
    if (b < 2){
        const int (*part)[NN] = (b == 0) ? g_part_a : g_part_d;
        int* off = (b == 0) ? g_off_a : g_off_d;
        int* tkt = (b == 0) ? g_tkt_a : g_tkt_d;
        __shared__ int ts[256];
        int base = t*4;
        int v0=0, v1=0, v2=0, v3=0;
        #pragma unroll
        for (int p = 0; p < 16; p++){
            const int4 q = *reinterpret_cast<const int4*>(&part[p][base]);
            v0 += q.x; v1 += q.y; v2 += q.z; v3 += q.w;
        }
        int local = v0+v1+v2+v3;
        ts[t] = local; __syncthreads();
        for (int o = 1; o < 256; o <<= 1){
            int add = (t >= o) ? ts[t-o] : 0;
            __syncthreads();
            ts[t] += add;
            __syncthreads();
        }
        int excl = ts[t] - local;
        int o0 = excl, o1 = o0+v0, o2 = o1+v1, o3 = o2+v2;
        off[base]=o0; off[base+1]=o1; off[base+2]=o2; off[base+3]=o3;
        tkt[base]=o0; tkt[base+1]=o1; tkt[base+2]=o2; tkt[base+3]=o3;
        if (t == 255) off[NN] = o3 + v3;
        if (b == 0){
            g_dinv[base+0] = rsqrtf((float)(v0+1));
            g_dinv[base+1] = rsqrtf((float)(v1+1));
            g_dinv[base+2] = rsqrtf((float)(v2+1));
            g_dinv[base+3] = rsqrtf((float)(v3+1));
        }
    } else {
        int n = (b-2)*256 + t;
        g_selfe1[n] = __expf(lrelu(g_als1[n] + g_ald1[n] + g_ewmean*g_c1));
    }
}

// ---------------- K2: CSR fill + packed weights ----------------
__global__ __launch_bounds__(256) void k2(const int* __restrict__ eia, const int* __restrict__ eid,
                                          const float* __restrict__ ew){
    int b = blockIdx.x, t = threadIdx.x;
    if (b < 64){
        int e = b*256 + t;
        int s = eia[e], d = eia[EE + e];
        int pos = atomicAdd(&g_tkt_a[d], 1);
        g_pk_a[pos] = make_float2(g_dinv[s], __int_as_float(s));
    } else {
        int e = (b-64)*256 + t;
        int s = eid[e], d = eid[EE + e];
        float w = ew[e];
        int pos = atomicAdd(&g_tkt_d[d], 1);
        float w1 = __expf(lrelu(g_als1[s] + g_ald1[d] + w*g_c1));
        g_pk_d1[pos] = make_float2(w1, __int_as_float(s));
        g_dst_d[pos] = d;
        g_ewp[pos] = w;
    }
}

// ---------------- K3: GCN1 gather + GAT1 gather ----------------
__global__ __launch_bounds__(256) void k3(const float* __restrict__ bg1, const float* __restrict__ bgat1){
    int b = blockIdx.x;
    int node = ((b & 127) << 3) + (threadIdx.x >> 5);
    if (b < 128) gather_gcn(g_hg1, bg1, g_xa1, node);
    else         gather_gat(g_ha1, g_pk_d1, g_selfe1, bgat1, g_xd1, node);
}

// ---------------- K4: GEMM2 x2 ----------------
__global__ __launch_bounds__(256) void k4(const float* __restrict__ Wg2, const float* __restrict__ Wa2,
                                          const float* __restrict__ as2, const float* __restrict__ ad2){
    __shared__ __align__(16) float xs[8*68];
    __shared__ float sred[16];
    int b = blockIdx.x, t = threadIdx.x;
    int col = t & 63, rg = t >> 6;
    float acc[2];
    if (b < 128){
        int n0 = b*8;
        LdRaw64 ld{g_xa1};
        load_tile8<64>(xs, n0, ld);
        compute_tile8<64>(xs, Wg2, col, rg, acc);
        #pragma unroll
        for (int i = 0; i < 2; i++) g_hg2[(n0 + rg*2 + i)*64 + col] = acc[i];
    } else {
        int n0 = (b-128)*8;
        LdRaw64 ld{g_xd1};
        load_tile8<64>(xs, n0, ld);
        compute_tile8<64>(xs, Wa2, col, rg, acc);
        #pragma unroll
        for (int i = 0; i < 2; i++) g_ha2[(n0 + rg*2 + i)*64 + col] = acc[i];
        attn_reduce8(acc[0], acc[1], acc[0], acc[1], as2[col], ad2[col],
                     g_als2, g_ald2, n0, rg, sred);
    }
}

// ---------------- K5: GCN2 gather + w2 pack + selfe2 ----------------
__global__ __launch_bounds__(256) void k5(const float* __restrict__ bg2){
    int b = blockIdx.x, t = threadIdx.x;
    if (b < 128){
        gather_gcn(g_hg2, bg2, g_xa2, b*8 + (t >> 5));
    } else if (b < 192){
        int p = (b-128)*256 + t;
        float2 q = g_pk_d1[p];
        int s = __float_as_int(q.y);
        int d = g_dst_d[p];
        float w2 = __expf(lrelu(g_als2[s] + g_ald2[d] + g_ewp[p]*g_c2));
        g_pk_d2[p] = make_float2(w2, q.y);
    } else {
        int n = (b-192)*256 + t;
        g_selfe2[n] = __expf(lrelu(g_als2[n] + g_ald2[n] + g_ewmean*g_c2));
    }
}

// ---------------- K6: GAT2 gather ----------------
__global__ __launch_bounds__(256) void k6(const float* __restrict__ bgat2){
    gather_gat(g_ha2, g_pk_d2, g_selfe2, bgat2, g_xd2, blockIdx.x*8 + (threadIdx.x >> 5));
}

// ---------------- K7: mix + GCN3 GEMM ----------------
__global__ __launch_bounds__(256) void k7(const float* __restrict__ Wg3){
    __shared__ __align__(16) float xs[8*68];
    int n0 = blockIdx.x*8;
    LdMix ld{};
    load_tile8<64>(xs, n0, ld);
    int col = threadIdx.x & 63, rg = threadIdx.x >> 6;
    float acc[2];
    compute_tile8<64>(xs, Wg3, col, rg, acc);
    #pragma unroll
    for (int i = 0; i < 2; i++) g_hg3[(n0 + rg*2 + i)*64 + col] = acc[i];
}

// ---------------- K8: GCN3 gather ----------------
__global__ __launch_bounds__(256) void k8(const float* __restrict__ bg3){
    gather_gcn(g_hg3, bg3, g_h3, blockIdx.x*8 + (threadIdx.x >> 5));
}

// ---------------- K9: predictor GEMM + rowsums ----------------
__global__ __launch_bounds__(256) void k9(const float* __restrict__ Wp1, const float* __restrict__ bp1,
                                          const float* __restrict__ Wp2){
    __shared__ __align__(16) float xs[8*68];
    __shared__ float sred[16];
    int n0 = blockIdx.x*8;
    LdRaw64 ld{g_h3};
    load_tile8<64>(xs, n0, ld);
    int col = threadIdx.x & 63, rg = threadIdx.x >> 6;
    float acc1[2], acc2[2];
    compute_tile8<64>(xs, Wp1, col, rg, acc1);
    float bb = bp1[col];
    acc1[0] += bb; acc1[1] += bb;
    #pragma unroll
    for (int i = 0; i < 2; i++) g_h1p[(n0 + rg*2 + i)*64 + col] = acc1[i];
    compute_tile8<64>(xs, Wp1 + 64*64, col, rg, acc2);
    float2 o; o.x = acc2[0]; o.y = acc2[1];
    *reinterpret_cast<float2*>(g_h2pT + col*NN + n0 + rg*2) = o;
    float w2 = __ldg(Wp2 + col);
    attn_reduce8(acc1[0], acc1[1], acc2[0], acc2[1], w2, w2, g_rs1, g_rs2, n0, rg, sred);
}

// ---------------- K10: all-pairs predictor, abs-identity + f32x2 ----------------
// logits = 0.5*(rs1[i]+rs2[j]) + bp2 + sum_h (0.5*w_h)*|h1p[i,h]+h2p[j,h]|
__global__ __launch_bounds__(256) void k10(const float* __restrict__ Wp2, const float* __restrict__ bp2,
                                           float* __restrict__ out){
    extern __shared__ __align__(16) char smem[];
    ull*   s1d  = (ull*)smem;                         // [64][65] dup pairs
    float* s2f  = (float*)(smem + 64*65*8);           // [64][68] h-major
    ull*   swpd = (ull*)(smem + 64*65*8 + 64*68*4);   // [64] dup 0.5*w
    int bi = blockIdx.x >> 4, bj = blockIdx.x & 15;
    int i0 = bi*64, j0 = bj*64, t = threadIdx.x;
    {
        int row = t >> 2, seg = (t & 3)*16;
        const float* src = g_h1p + (i0+row)*64 + seg;
        ull* dst = s1d + row*65 + seg;
        #pragma unroll
        for (int k = 0; k < 4; k++){
            float4 v = *(const float4*)(src + k*4);
            dst[k*4+0] = fdup(v.x); dst[k*4+1] = fdup(v.y);
            dst[k*4+2] = fdup(v.z); dst[k*4+3] = fdup(v.w);
        }
    }
    {
        int h = t >> 2, seg = (t & 3)*16;
        const float4* src = (const float4*)(g_h2pT + h*NN + j0 + seg);
        float4* dst = (float4*)(s2f + h*68 + seg);
        dst[0]=src[0]; dst[1]=src[1]; dst[2]=src[2]; dst[3]=src[3];
    }
    if (t < 64) swpd[t] = fdup(0.5f*__ldg(Wp2 + t));
    __syncthreads();

    int tx = t & 15, ty = t >> 4;
    const ull ABS2 = 0x7FFFFFFF7FFFFFFFULL;
    ull acc[4][2];
    #pragma unroll
    for (int a = 0; a < 4; a++){ acc[a][0] = 0ULL; acc[a][1] = 0ULL; }
    const ull* s1p = s1d + (ty*4)*65;
    const float* r2base = s2f + tx*4;

    #pragma unroll 8
    for (int h = 0; h < 64; h++){
        ull w2 = swpd[h];
        ull r2a = *(const ull*)(r2base + h*68);
        ull r2b = *(const ull*)(r2base + h*68 + 2);
        #pragma unroll
        for (int a = 0; a < 4; a++){
            ull r1 = s1p[a*65 + h];
            ull t0 = f2add(r1, r2a) & ABS2;
            ull t1 = f2add(r1, r2b) & ABS2;
            acc[a][0] = f2fma(t0, w2, acc[a][0]);
            acc[a][1] = f2fma(t1, w2, acc[a][1]);
        }
    }
    float bb = bp2[0];
    float hr2[4];
    #pragma unroll
    for (int c = 0; c < 4; c++) hr2[c] = 0.5f*__ldg(g_rs2 + j0 + tx*4 + c);
    #pragma unroll
    for (int a = 0; a < 4; a++){
        int row = i0 + ty*4 + a;
        float base = 0.5f*__ldg(g_rs1 + row) + bb;
        float l0 = f2lo(acc[a][0]) + base + hr2[0];
        float l1 = f2hi(acc[a][0]) + base + hr2[1];
        float l2 = f2lo(acc[a][1]) + base + hr2[2];
        float l3 = f2hi(acc[a][1]) + base + hr2[3];
        float4 o;
        o.x = 1.0f / (1.0f + __expf(-l0));
        o.y = 1.0f / (1.0f + __expf(-l1));
        o.z = 1.0f / (1.0f + __expf(-l2));
        o.w = 1.0f / (1.0f + __expf(-l3));
        *reinterpret_cast<float4*>(out + row*NN + j0 + tx*4) = o;
    }
}

// ---------------- launch ----------------
extern "C" void kernel_launch(void* const* d_in, const int* in_sizes, int n_in,
                              void* d_out, int out_size){
    const float* x    = (const float*)d_in[0];
    const int*   eia  = (const int*)  d_in[1];
    const int*   eid  = (const int*)  d_in[2];
    const float* ew   = (const float*)d_in[3];
    const float* Wg1  = (const float*)d_in[4];
    const float* bg1  = (const float*)d_in[5];
    const float* Wa1  = (const float*)d_in[6];
    const float* as1  = (const float*)d_in[7];
    const float* ad1  = (const float*)d_in[8];
    const float* we1  = (const float*)d_in[9];
    const float* ae1  = (const float*)d_in[10];
    const float* bgat1= (const float*)d_in[11];
    const float* Wg2  = (const float*)d_in[12];
    const float* bg2  = (const float*)d_in[13];
    const float* Wa2  = (const float*)d_in[14];
    const float* as2  = (const float*)d_in[15];
    const float* ad2  = (const float*)d_in[16];
    const float* we2  = (const float*)d_in[17];
    const float* ae2  = (const float*)d_in[18];
    const float* bgat2= (const float*)d_in[19];
    const float* Wg3  = (const float*)d_in[20];
    const float* bg3  = (const float*)d_in[21];
    const float* Wp1  = (const float*)d_in[22];
    const float* bp1  = (const float*)d_in[23];
    const float* Wp2  = (const float*)d_in[24];
    const float* bp2  = (const float*)d_in[25];
    float* out = (float*)d_out;

    static int s_attr_done = 0;
    const int k10_smem = 64*65*8 + 64*68*4 + 64*8;
    if (!s_attr_done){
        cudaFuncSetAttribute(k10, cudaFuncAttributeMaxDynamicSharedMemorySize, k10_smem);
        s_attr_done = 1;
    }

    k0<<<161, 256>>>(x, eia, eid, ew, Wg1, Wa1, as1, ad1, we1, ae1, we2, ae2);
    k1<<<6, 256>>>();
    k2<<<128, 256>>>(eia, eid, ew);
    k3<<<256, 256>>>(bg1, bgat1);
    k4<<<256, 256>>>(Wg2, Wa2, as2, ad2);
    k5<<<196, 256>>>(bg2);
    k6<<<128, 256>>>(bgat2);
    k7<<<128, 256>>>(Wg3);
    k8<<<128, 256>>>(bg3);
    k9<<<128, 256>>>(Wp1, bp1, Wp2);
    k10<<<256, 256, k10_smem>>>(Wp2, bp2, out);
}

// round 4
// speedup vs baseline: 1.3095x; 1.0042x over previous
#include <cuda_runtime.h>
#include <cuda_bf16.h>

#define NN 1024
#define HH 64
#define EE 16384
#define NB 148
#define NT 512

typedef unsigned long long ull;

// ---------------- scratch (device globals; no allocation) ----------------
__device__ __align__(16) float g_hg1[NN*HH], g_ha1[NN*HH], g_hg2[NN*HH], g_ha2[NN*HH], g_hg3[NN*HH];
__device__ __align__(16) float g_xa1[NN*HH], g_xd1[NN*HH], g_xa2[NN*HH], g_xd2[NN*HH], g_h3[NN*HH];
__device__ __align__(16) float g_h1p[NN*HH], g_h2pT[NN*HH];
__device__ float g_als1[NN], g_ald1[NN], g_als2[NN], g_ald2[NN];
__device__ float g_dinv[NN], g_selfe1[NN], g_selfe2[NN];
__device__ float g_rs1[NN], g_rs2[NN];
__device__ float g_va2[HH], g_vb2[HH];
__device__ float g_ewmean, g_c1, g_c2;

__device__ int g_part[2][8][NN];
__device__ int g_off_a[NN+1], g_off_d[NN+1];
__device__ int g_tkt_a[NN], g_tkt_d[NN];
__device__ __align__(8) float2 g_pk_a[EE];
__device__ __align__(8) float2 g_pk_d1[EE];
__device__ __align__(8) float2 g_pk_d2[EE];
__device__ int g_dst_d[EE];
__device__ float g_ewp[EE];

// barrier state (monotonic generation; replay-safe)
__device__ unsigned g_arrive = 0;
__device__ unsigned g_gen = 0;

__device__ __forceinline__ void gsync(){
    __syncthreads();
    if (threadIdx.x == 0){
        unsigned gen = *(volatile unsigned*)&g_gen;
        __threadfence();
        if (atomicAdd(&g_arrive, 1u) == gridDim.x - 1){
            atomicExch(&g_arrive, 0u);
            __threadfence();
            atomicAdd(&g_gen, 1u);
        } else {
            while (*(volatile unsigned*)&g_gen == gen) __nanosleep(64);
        }
    }
    __syncthreads();
}

// ---------------- helpers ----------------
__device__ __forceinline__ float lrelu(float v){ return v > 0.f ? v : 0.2f*v; }
__device__ __forceinline__ ull f2add(ull a, ull b){
    ull r; asm("add.rn.f32x2 %0, %1, %2;" : "=l"(r) : "l"(a), "l"(b)); return r; }
__device__ __forceinline__ ull f2fma(ull a, ull b, ull c){
    ull r; asm("fma.rn.f32x2 %0, %1, %2, %3;" : "=l"(r) : "l"(a), "l"(b), "l"(c)); return r; }
__device__ __forceinline__ float f2lo(ull v){ return __uint_as_float((unsigned)v); }
__device__ __forceinline__ float f2hi(ull v){ return __uint_as_float((unsigned)(v >> 32)); }
__device__ __forceinline__ ull fdup(float f){ ull u = __float_as_uint(f); return u | (u << 32); }
__device__ __forceinline__ ull fpack(float lo, float hi){
    return (ull)__float_as_uint(lo) | ((ull)__float_as_uint(hi) << 32); }

// ---------------- GEMM tiles: 16 nodes, 512 thr (col=t&63, rg=t>>6 -> 2 rows) ----------------
template<int K, class L>
__device__ __forceinline__ void load_tile16(float* xs, int n0, const L& ld){
    const int LD = K + 4;
    for (int idx = threadIdx.x; idx < 16*K; idx += NT){
        int ln = idx / K, k = idx - ln*K;
        xs[ln*LD + k] = ld(n0 + ln, k);
    }
    __syncthreads();
}

template<int K>
__device__ __forceinline__ void compute_tile16(const float* xs, const float* __restrict__ W,
                                               int col, int rg, float acc[2]){
    const int LD = K + 4;
    const float* x0 = xs + rg*2*LD;
    acc[0]=0.f; acc[1]=0.f;
    #pragma unroll
    for (int k = 0; k < K; k += 4){
        float w0 = __ldg(W + (k+0)*64 + col);
        float w1 = __ldg(W + (k+1)*64 + col);
        float w2 = __ldg(W + (k+2)*64 + col);
        float w3 = __ldg(W + (k+3)*64 + col);
        #pragma unroll
        for (int i = 0; i < 2; i++){
            const float4 xv = *reinterpret_cast<const float4*>(x0 + i*LD + k);
            acc[i] = fmaf(xv.x, w0, acc[i]);
            acc[i] = fmaf(xv.y, w1, acc[i]);
            acc[i] = fmaf(xv.z, w2, acc[i]);
            acc[i] = fmaf(xv.w, w3, acc[i]);
        }
    }
}

struct LdRaw128 { const float* x;
    __device__ float operator()(int n, int k) const { return x[n*128 + k]; } };
struct LdRaw64 { const float* x;
    __device__ float operator()(int n, int k) const { return x[n*64 + k]; } };
struct LdMix {
    __device__ float operator()(int n, int k) const {
        return 0.7f*g_xa2[n*64+k] + 0.3f*g_xd2[n*64+k]; } };

// ---------------- row reductions (16-node tile, 512 thr) ----------------
__device__ __forceinline__ void reduce_rows_dual(float a0, float a1, float wA, float wB,
                                                 float* outA, float* outB, int n0, float* sred){
    int t = threadIdx.x;
    if (t < 32) sred[t] = 0.f;
    __syncthreads();
    float pA0=a0*wA, pA1=a1*wA, pB0=a0*wB, pB1=a1*wB;
    #pragma unroll
    for (int o = 16; o > 0; o >>= 1){
        pA0 += __shfl_down_sync(0xffffffffu, pA0, o);
        pA1 += __shfl_down_sync(0xffffffffu, pA1, o);
        pB0 += __shfl_down_sync(0xffffffffu, pB0, o);
        pB1 += __shfl_down_sync(0xffffffffu, pB1, o);
    }
    if ((t & 31) == 0){
        int rg = t >> 6;
        atomicAdd(&sred[rg*2+0], pA0);
        atomicAdd(&sred[rg*2+1], pA1);
        atomicAdd(&sred[16+rg*2+0], pB0);
        atomicAdd(&sred[16+rg*2+1], pB1);
    }
    __syncthreads();
    if (t < 16) outA[n0+t] = sred[t];
    else if (t < 32) outB[n0+t-16] = sred[t];
}

__device__ __forceinline__ void reduce_rows_single(float a0, float a1, float w,
                                                   float* outv, int n0, float* sred){
    int t = threadIdx.x;
    if (t < 16) sred[t] = 0.f;
    __syncthreads();
    float p0 = a0*w, p1 = a1*w;
    #pragma unroll
    for (int o = 16; o > 0; o >>= 1){
        p0 += __shfl_down_sync(0xffffffffu, p0, o);
        p1 += __shfl_down_sync(0xffffffffu, p1, o);
    }
    if ((t & 31) == 0){
        int rg = t >> 6;
        atomicAdd(&sred[rg*2+0], p0);
        atomicAdd(&sred[rg*2+1], p1);
    }
    __syncthreads();
    if (t < 16) outv[n0+t] = sred[t];
}

// ---------------- gathers: warp per node; lane = part*16 + col4 ----------------
__device__ __forceinline__ void gather_gcn(const float* __restrict__ h, const float* __restrict__ bias,
                                           float* __restrict__ out, int node){
    int lane = threadIdx.x & 31;
    int col4 = lane & 15, part = lane >> 4;
    const float2* __restrict__ pk = g_pk_a;
    int beg = g_off_a[node], end = g_off_a[node+1];
    float4 acc = make_float4(0.f,0.f,0.f,0.f);
    int i = beg + part;
    for (; i + 6 < end; i += 8){
        float2 q0 = __ldg(pk+i),   q1 = __ldg(pk+i+2);
        float2 q2 = __ldg(pk+i+4), q3 = __ldg(pk+i+6);
        int s0=__float_as_int(q0.y), s1=__float_as_int(q1.y);
        int s2=__float_as_int(q2.y), s3=__float_as_int(q3.y);
        float4 h0 = *(const float4*)(h + s0*64 + col4*4);
        float4 h1 = *(const float4*)(h + s1*64 + col4*4);
        float4 h2 = *(const float4*)(h + s2*64 + col4*4);
        float4 h3 = *(const float4*)(h + s3*64 + col4*4);
        acc.x = fmaf(q0.x,h0.x, fmaf(q1.x,h1.x, fmaf(q2.x,h2.x, fmaf(q3.x,h3.x, acc.x))));
        acc.y = fmaf(q0.x,h0.y, fmaf(q1.x,h1.y, fmaf(q2.x,h2.y, fmaf(q3.x,h3.y, acc.y))));
        acc.z = fmaf(q0.x,h0.z, fmaf(q1.x,h1.z, fmaf(q2.x,h2.z, fmaf(q3.x,h3.z, acc.z))));
        acc.w = fmaf(q0.x,h0.w, fmaf(q1.x,h1.w, fmaf(q2.x,h2.w, fmaf(q3.x,h3.w, acc.w))));
    }
    for (; i < end; i += 2){
        float2 q = __ldg(pk+i);
        int s = __float_as_int(q.y);
        float4 hv = *(const float4*)(h + s*64 + col4*4);
        acc.x = fmaf(q.x,hv.x,acc.x); acc.y = fmaf(q.x,hv.y,acc.y);
        acc.z = fmaf(q.x,hv.z,acc.z); acc.w = fmaf(q.x,hv.w,acc.w);
    }
    acc.x += __shfl_xor_sync(0xffffffffu, acc.x, 16);
    acc.y += __shfl_xor_sync(0xffffffffu, acc.y, 16);
    acc.z += __shfl_xor_sync(0xffffffffu, acc.z, 16);
    acc.w += __shfl_xor_sync(0xffffffffu, acc.w, 16);
    if (part == 0){
        float dd = g_dinv[node];
        float4 hs = *(const float4*)(h + node*64 + col4*4);
        float4 bb = *(const float4*)(bias + col4*4);
        float4 o;
        o.x = fmaxf(fmaf(dd, fmaf(dd, hs.x, acc.x), bb.x), 0.f);
        o.y = fmaxf(fmaf(dd, fmaf(dd, hs.y, acc.y), bb.y), 0.f);
        o.z = fmaxf(fmaf(dd, fmaf(dd, hs.z, acc.z), bb.z), 0.f);
        o.w = fmaxf(fmaf(dd, fmaf(dd, hs.w, acc.w), bb.w), 0.f);
        *(float4*)(out + node*64 + col4*4) = o;
    }
}

template<bool EPI>
__device__ __forceinline__ void gather_gat(const float* __restrict__ h, const float2* __restrict__ pk,
                                           const float* __restrict__ selfe, const float* __restrict__ bias,
                                           float* __restrict__ out, int node){
    int lane = threadIdx.x & 31;
    int col4 = lane & 15, part = lane >> 4;
    int beg = g_off_d[node], end = g_off_d[node+1];
    float4 acc = make_float4(0.f,0.f,0.f,0.f);
    float den = 0.f;
    int i = beg + part;
    for (; i + 6 < end; i += 8){
        float2 q0 = __ldg(pk+i),   q1 = __ldg(pk+i+2);
        float2 q2 = __ldg(pk+i+4), q3 = __ldg(pk+i+6);
        int s0=__float_as_int(q0.y), s1=__float_as_int(q1.y);
        int s2=__float_as_int(q2.y), s3=__float_as_int(q3.y);
        float4 h0 = *(const float4*)(h + s0*64 + col4*4);
        float4 h1 = *(const float4*)(h + s1*64 + col4*4);
        float4 h2 = *(const float4*)(h + s2*64 + col4*4);
        float4 h3 = *(const float4*)(h + s3*64 + col4*4);
        den += (q0.x+q1.x)+(q2.x+q3.x);
        acc.x = fmaf(q0.x,h0.x, fmaf(q1.x,h1.x, fmaf(q2.x,h2.x, fmaf(q3.x,h3.x, acc.x))));
        acc.y = fmaf(q0.x,h0.y, fmaf(q1.x,h1.y, fmaf(q2.x,h2.y, fmaf(q3.x,h3.y, acc.y))));
        acc.z = fmaf(q0.x,h0.z, fmaf(q1.x,h1.z, fmaf(q2.x,h2.z, fmaf(q3.x,h3.z, acc.z))));
        acc.w = fmaf(q0.x,h0.w, fmaf(q1.x,h1.w, fmaf(q2.x,h2.w, fmaf(q3.x,h3.w, acc.w))));
    }
    for (; i < end; i += 2){
        float2 q = __ldg(pk+i);
        int s = __float_as_int(q.y);
        float4 hv = *(const float4*)(h + s*64 + col4*4);
        den += q.x;
        acc.x = fmaf(q.x,hv.x,acc.x); acc.y = fmaf(q.x,hv.y,acc.y);
        acc.z = fmaf(q.x,hv.z,acc.z); acc.w = fmaf(q.x,hv.w,acc.w);
    }
    acc.x += __shfl_xor_sync(0xffffffffu, acc.x, 16);
    acc.y += __shfl_xor_sync(0xffffffffu, acc.y, 16);
    acc.z += __shfl_xor_sync(0xffffffffu, acc.z, 16);
    acc.w += __shfl_xor_sync(0xffffffffu, acc.w, 16);
    den   += __shfl_xor_sync(0xffffffffu, den, 16);
    if (part == 0){
        float es = selfe[node];
        float inv = 1.0f / (den + es);
        float4 hs = *(const float4*)(h + node*64 + col4*4);
        float4 bb = *(const float4*)(bias + col4*4);
        float4 o;
        o.x = fmaxf(fmaf(es, hs.x, acc.x)*inv + bb.x, 0.f);
        o.y = fmaxf(fmaf(es, hs.y, acc.y)*inv + bb.y, 0.f);
        o.z = fmaxf(fmaf(es, hs.z, acc.z)*inv + bb.z, 0.f);
        o.w = fmaxf(fmaf(es, hs.w, acc.w)*inv + bb.w, 0.f);
        *(float4*)(out + node*64 + col4*4) = o;
        if (EPI){
            int c0 = col4*4;
            float pa = o.x*g_va2[c0] + o.y*g_va2[c0+1] + o.z*g_va2[c0+2] + o.w*g_va2[c0+3];
            float pb = o.x*g_vb2[c0] + o.y*g_vb2[c0+1] + o.z*g_vb2[c0+2] + o.w*g_vb2[c0+3];
            #pragma unroll
            for (int off = 8; off > 0; off >>= 1){
                pa += __shfl_down_sync(0x0000FFFFu, pa, off);
                pb += __shfl_down_sync(0x0000FFFFu, pb, off);
            }
            if (col4 == 0){ g_als2[node] = pa; g_ald2[node] = pb; }
        }
    }
}

// ---------------- the single persistent kernel ----------------
__global__ void __launch_bounds__(NT, 1) kmain(
    const float* __restrict__ x, const int* __restrict__ eia, const int* __restrict__ eid,
    const float* __restrict__ ew,
    const float* __restrict__ Wg1, const float* __restrict__ bg1,
    const float* __restrict__ Wa1, const float* __restrict__ as1, const float* __restrict__ ad1,
    const float* __restrict__ we1, const float* __restrict__ ae1, const float* __restrict__ bgat1,
    const float* __restrict__ Wg2, const float* __restrict__ bg2,
    const float* __restrict__ Wa2, const float* __restrict__ as2, const float* __restrict__ ad2,
    const float* __restrict__ we2, const float* __restrict__ ae2, const float* __restrict__ bgat2,
    const float* __restrict__ Wg3, const float* __restrict__ bg3,
    const float* __restrict__ Wp1, const float* __restrict__ bp1,
    const float* __restrict__ Wp2, const float* __restrict__ bp2,
    float* __restrict__ out)
{
    extern __shared__ __align__(16) char sm[];
    float* xs   = (float*)sm;                 // gemm tile (<= 16*132*4 = 8448B)
    float* sred = (float*)(sm + 8448);        // 32 floats
    int vb = blockIdx.x;
    int t = threadIdx.x;
    int wid = t >> 5;

    // ===== P0: GEMM1 (Wg 0-63, Wa 64-127) + hist (128-143) + scalars (144) =====
    if (vb < 64){
        int n0 = vb*16;
        load_tile16<128>(xs, n0, LdRaw128{x});
        int col = t & 63, rg = t >> 6;
        float acc[2];
        compute_tile16<128>(xs, Wg1, col, rg, acc);
        #pragma unroll
        for (int i = 0; i < 2; i++) g_hg1[(n0 + rg*2 + i)*64 + col] = acc[i];
    } else if (vb < 128){
        int n0 = (vb-64)*16;
        load_tile16<128>(xs, n0, LdRaw128{x});
        int col = t & 63, rg = t >> 6;
        float acc[2];
        compute_tile16<128>(xs, Wa1, col, rg, acc);
        #pragma unroll
        for (int i = 0; i < 2; i++) g_ha1[(n0 + rg*2 + i)*64 + col] = acc[i];
        reduce_rows_dual(acc[0], acc[1], as1[col], ad1[col], g_als1, g_ald1, n0, sred);
    } else if (vb < 144){
        int vv = vb - 128;
        int gg = vv >> 3, seg = vv & 7;
        int* hc = (int*)sm;
        for (int i = t; i < NN; i += NT) hc[i] = 0;
        __syncthreads();
        const int* dst = (gg ? eid : eia) + EE + seg*2048;
        #pragma unroll
        for (int it = 0; it < 4; it++) atomicAdd(&hc[dst[it*NT + t]], 1);
        __syncthreads();
        for (int i = t; i < NN; i += NT) g_part[gg][seg][i] = hc[i];
    } else if (vb == 144){
        float* sr = (float*)sm;
        float s = 0.f;
        for (int i = t; i < EE; i += NT) s += ew[i];
        sr[t] = s; __syncthreads();
        for (int o = 256; o > 0; o >>= 1){ if (t < o) sr[t] += sr[t+o]; __syncthreads(); }
        if (t == 0) g_ewmean = sr[0] * (1.0f/EE);
        __syncthreads();
        sr[t] = (t < 64) ? we1[t]*ae1[t] : 0.f; __syncthreads();
        for (int o = 256; o > 0; o >>= 1){ if (t < o) sr[t] += sr[t+o]; __syncthreads(); }
        if (t == 0) g_c1 = sr[0];
        __syncthreads();
        sr[t] = (t < 64) ? we2[t]*ae2[t] : 0.f; __syncthreads();
        for (int o = 256; o > 0; o >>= 1){ if (t < o) sr[t] += sr[t+o]; __syncthreads(); }
        if (t == 0) g_c2 = sr[0];
        if (t < 64){
            float pa = 0.f, pb = 0.f;
            #pragma unroll 8
            for (int c = 0; c < 64; c++){
                float w = Wa2[t*64 + c];
                pa = fmaf(w, as2[c], pa);
                pb = fmaf(w, ad2[c], pb);
            }
            g_va2[t] = pa; g_vb2[t] = pb;
        }
    }
    gsync();

    // ===== P1: scan (0,1) + selfe1 (2,3) =====
    if (vb < 2){
        int* tsm = (int*)sm;
        int v0=0, v1=0, v2=0, v3=0, local=0;
        if (t < 256){
            int base = t*4;
            #pragma unroll
            for (int p = 0; p < 8; p++){
                const int4 q = *reinterpret_cast<const int4*>(&g_part[vb][p][base]);
                v0 += q.x; v1 += q.y; v2 += q.z; v3 += q.w;
            }
            local = v0+v1+v2+v3;
            tsm[t] = local;
        }
        __syncthreads();
        for (int o = 1; o < 256; o <<= 1){
            int add = (t >= o && t < 256) ? tsm[t-o] : 0;
            __syncthreads();
            if (t < 256) tsm[t] += add;
            __syncthreads();
        }
        if (t < 256){
            int excl = tsm[t] - local;
            int base = t*4;
            int o0 = excl, o1 = o0+v0, o2 = o1+v1, o3 = o2+v2;
            int* off = vb ? g_off_d : g_off_a;
            int* tkt = vb ? g_tkt_d : g_tkt_a;
            off[base]=o0; off[base+1]=o1; off[base+2]=o2; off[base+3]=o3;
            tkt[base]=o0; tkt[base+1]=o1; tkt[base+2]=o2; tkt[base+3]=o3;
            if (t == 255) off[NN] = o3 + v3;
            if (vb == 0){
                g_dinv[base+0] = rsqrtf((float)(v0+1));
                g_dinv[base+1] = rsqrtf((float)(v1+1));
                g_dinv[base+2] = rsqrtf((float)(v2+1));
                g_dinv[base+3] = rsqrtf((float)(v3+1));
            }
        }
    } else if (vb < 4){
        int n = (vb-2)*NT + t;
        g_selfe1[n] = __expf(lrelu(g_als1[n] + g_ald1[n] + g_ewmean*g_c1));
    }
    gsync();

    // ===== P2: CSR fill A (0-31) + fill/pack D (32-63) =====
    if (vb < 32){
        int e = vb*NT + t;
        int s = eia[e], d = eia[EE + e];
        int pos = atomicAdd(&g_tkt_a[d], 1);
        g_pk_a[pos] = make_float2(g_dinv[s], __int_as_float(s));
    } else if (vb < 64){
        int e = (vb-32)*NT + t;
        int s = eid[e], d = eid[EE + e];
        float w = ew[e];
        int pos = atomicAdd(&g_tkt_d[d], 1);
        g_pk_d1[pos] = make_float2(__expf(lrelu(g_als1[s] + g_ald1[d] + w*g_c1)),
                                   __int_as_float(s));
        g_dst_d[pos] = d;
        g_ewp[pos] = w;
    }
    gsync();

    // ===== P3: GCN1 gather (0-63) + GAT1 gather w/ als2-ald2 epilogue (64-127) =====
    if (vb < 64) gather_gcn(g_hg1, bg1, g_xa1, vb*16 + wid);
    else if (vb < 128) gather_gat<true>(g_ha1, g_pk_d1, g_selfe1, bgat1, g_xd1, (vb-64)*16 + wid);
    gsync();

    // ===== P4: GEMM2 (hg2 0-63, ha2 64-127) + pack w2 (128-143) + selfe2 (144-145) =====
    if (vb < 64){
        int n0 = vb*16;
        load_tile16<64>(xs, n0, LdRaw64{g_xa1});
        int col = t & 63, rg = t >> 6;
        float acc[2];
        compute_tile16<64>(xs, Wg2, col, rg, acc);
        #pragma unroll
        for (int i = 0; i < 2; i++) g_hg2[(n0 + rg*2 + i)*64 + col] = acc[i];
    } else if (vb < 128){
        int n0 = (vb-64)*16;
        load_tile16<64>(xs, n0, LdRaw64{g_xd1});
        int col = t & 63, rg = t >> 6;
        float acc[2];
        compute_tile16<64>(xs, Wa2, col, rg, acc);
        #pragma unroll
        for (int i = 0; i < 2; i++) g_ha2[(n0 + rg*2 + i)*64 + col] = acc[i];
    } else if (vb < 144){
        int base = (vb-128)*1024;
        #pragma unroll
        for (int it = 0; it < 2; it++){
            int p = base + it*NT + t;
            float2 q = g_pk_d1[p];
            int s = __float_as_int(q.y);
            int d = g_dst_d[p];
            g_pk_d2[p] = make_float2(__expf(lrelu(g_als2[s] + g_ald2[d] + g_ewp[p]*g_c2)), q.y);
        }
    } else if (vb < 146){
        int n = (vb-144)*NT + t;
        g_selfe2[n] = __expf(lrelu(g_als2[n] + g_ald2[n] + g_ewmean*g_c2));
    }
    gsync();

    // ===== P5: GCN2 gather (0-63) + GAT2 gather (64-127) =====
    if (vb < 64) gather_gcn(g_hg2, bg2, g_xa2, vb*16 + wid);
    else if (vb < 128) gather_gat<false>(g_ha2, g_pk_d2, g_selfe2, bgat2, g_xd2, (vb-64)*16 + wid);
    gsync();

    // ===== P6: mix + GEMM3 (0-63) =====
    if (vb < 64){
        int n0 = vb*16;
        load_tile16<64>(xs, n0, LdMix{});
        int col = t & 63, rg = t >> 6;
        float acc[2];
        compute_tile16<64>(xs, Wg3, col, rg, acc);
        #pragma unroll
        for (int i = 0; i < 2; i++) g_hg3[(n0 + rg*2 + i)*64 + col] = acc[i];
    }
    gsync();

    // ===== P7: GCN3 gather (0-63) =====
    if (vb < 64) gather_gcn(g_hg3, bg3, g_h3, vb*16 + wid);
    gsync();

    // ===== P8: predictor GEMM lo (0-63: h1p + rs1) / hi (64-127: h2pT + rs2) =====
    if (vb < 64){
        int n0 = vb*16;
        load_tile16<64>(xs, n0, LdRaw64{g_h3});
        int col = t & 63, rg = t >> 6;
        float acc[2];
        compute_tile16<64>(xs, Wp1, col, rg, acc);
        float bb = bp1[col];
        acc[0] += bb; acc[1] += bb;
        #pragma unroll
        for (int i = 0; i < 2; i++) g_h1p[(n0 + rg*2 + i)*64 + col] = acc[i];
        reduce_rows_single(acc[0], acc[1], __ldg(Wp2 + col), g_rs1, n0, sred);
    } else if (vb < 128){
        int n0 = (vb-64)*16;
        load_tile16<64>(xs, n0, LdRaw64{g_h3});
        int col = t & 63, rg = t >> 6;
        float acc[2];
        compute_tile16<64>(xs, Wp1 + 64*64, col, rg, acc);
        float2 o; o.x = acc[0]; o.y = acc[1];
        *reinterpret_cast<float2*>(g_h2pT + col*NN + n0 + rg*2) = o;
        reduce_rows_single(acc[0], acc[1], __ldg(Wp2 + col), g_rs2, n0, sred);
    }
    gsync();

    // ===== P9: all-pairs predictor, 64x128 tiles (0-127) =====
    if (vb < 128){
        ull* s1d  = (ull*)sm;                        // [64][65] dup pairs   (33280B)
        ull* s2a  = (ull*)(sm + 33280);              // [64][33] cols 0,1 mod4 (16896B)
        ull* s2b  = (ull*)(sm + 33280 + 16896);      // [64][33] cols 2,3 mod4 (16896B)
        ull* swpd = (ull*)(sm + 33280 + 33792);      // [64] dup 0.5*w       (512B)
        int bi = vb >> 3, bj = vb & 7;
        int i0 = bi*64, j0 = bj*128;
        for (int i = t; i < 1024; i += NT){
            int row = i >> 4, seg = (i & 15)*4;
            float4 v = *(const float4*)(g_h1p + (i0+row)*64 + seg);
            ull* d = s1d + row*65 + seg;
            d[0] = fdup(v.x); d[1] = fdup(v.y); d[2] = fdup(v.z); d[3] = fdup(v.w);
        }
        for (int i = t; i < 2048; i += NT){
            int h = i >> 5, j4 = i & 31;
            float4 v = *(const float4*)(g_h2pT + h*NN + j0 + j4*4);
            s2a[h*33 + j4] = fpack(v.x, v.y);
            s2b[h*33 + j4] = fpack(v.z, v.w);
        }
        if (t < 64) swpd[t] = fdup(0.5f*__ldg(Wp2 + t));
        __syncthreads();

        int tx = t & 31, ty = t >> 5;
        const ull ABS2 = 0x7FFFFFFF7FFFFFFFULL;
        ull acc[4][2];
        #pragma unroll
        for (int a = 0; a < 4; a++){ acc[a][0] = 0ULL; acc[a][1] = 0ULL; }
        const ull* s1p = s1d + (ty*4)*65;

        #pragma unroll 8
        for (int h = 0; h < 64; h++){
            ull w2 = swpd[h];
            ull r2a = s2a[h*33 + tx];
            ull r2b = s2b[h*33 + tx];
            #pragma unroll
            for (int a = 0; a < 4; a++){
                ull r1 = s1p[a*65 + h];
                ull t0 = f2add(r1, r2a) & ABS2;
                ull t1 = f2add(r1, r2b) & ABS2;
                acc[a][0] = f2fma(t0, w2, acc[a][0]);
                acc[a][1] = f2fma(t1, w2, acc[a][1]);
            }
        }
        float bb = bp2[0];
        float hr2[4];
        #pragma unroll
        for (int c = 0; c < 4; c++) hr2[c] = 0.5f*__ldg(g_rs2 + j0 + tx*4 + c);
        #pragma unroll
        for (int a = 0; a < 4; a++){
            int row = i0 + ty*4 + a;
            float base = 0.5f*__ldg(g_rs1 + row) + bb;
            float l0 = f2lo(acc[a][0]) + base + hr2[0];
            float l1 = f2hi(acc[a][0]) + base + hr2[1];
            float l2 = f2lo(acc[a][1]) + base + hr2[2];
            float l3 = f2hi(acc[a][1]) + base + hr2[3];
            float4 o;
            o.x = 1.0f / (1.0f + __expf(-l0));
            o.y = 1.0f / (1.0f + __expf(-l1));
            o.z = 1.0f / (1.0f + __expf(-l2));
            o.w = 1.0f / (1.0f + __expf(-l3));
            *reinterpret_cast<float4*>(out + row*NN + j0 + tx*4) = o;
        }
    }
}

// ---------------- launch ----------------
extern "C" void kernel_launch(void* const* d_in, const int* in_sizes, int n_in,
                              void* d_out, int out_size){
    const float* x    = (const float*)d_in[0];
    const int*   eia  = (const int*)  d_in[1];
    const int*   eid  = (const int*)  d_in[2];
    const float* ew   = (const float*)d_in[3];
    const float* Wg1  = (const float*)d_in[4];
    const float* bg1  = (const float*)d_in[5];
    const float* Wa1  = (const float*)d_in[6];
    const float* as1  = (const float*)d_in[7];
    const float* ad1  = (const float*)d_in[8];
    const float* we1  = (const float*)d_in[9];
    const float* ae1  = (const float*)d_in[10];
    const float* bgat1= (const float*)d_in[11];
    const float* Wg2  = (const float*)d_in[12];
    const float* bg2  = (const float*)d_in[13];
    const float* Wa2  = (const float*)d_in[14];
    const float* as2  = (const float*)d_in[15];
    const float* ad2  = (const float*)d_in[16];
    const float* we2  = (const float*)d_in[17];
    const float* ae2  = (const float*)d_in[18];
    const float* bgat2= (const float*)d_in[19];
    const float* Wg3  = (const float*)d_in[20];
    const float* bg3  = (const float*)d_in[21];
    const float* Wp1  = (const float*)d_in[22];
    const float* bp1  = (const float*)d_in[23];
    const float* Wp2  = (const float*)d_in[24];
    const float* bp2  = (const float*)d_in[25];
    float* out = (float*)d_out;

    const int smem = 33280 + 33792 + 512;   // 67584 bytes
    static int s_attr_done = 0;
    if (!s_attr_done){
        cudaFuncSetAttribute(kmain, cudaFuncAttributeMaxDynamicSharedMemorySize, smem);
        s_attr_done = 1;
    }

    kmain<<<NB, NT, smem>>>(x, eia, eid, ew,
                            Wg1, bg1, Wa1, as1, ad1, we1, ae1, bgat1,
                            Wg2, bg2, Wa2, as2, ad2, we2, ae2, bgat2,
                            Wg3, bg3, Wp1, bp1, Wp2, bp2, out);
}

// round 5
// speedup vs baseline: 1.4855x; 1.1344x over previous
#include <cuda_runtime.h>
#include <cuda_bf16.h>

#define NN 1024
#define HH 64
#define EE 16384
#define NB 148
#define NT 512

typedef unsigned long long ull;

// ---------------- scratch (device globals; no allocation) ----------------
__device__ __align__(16) float g_hg1[NN*HH], g_ha1[NN*HH], g_hg2[NN*HH], g_ha2[NN*HH], g_hg3[NN*HH];
__device__ __align__(16) float g_h1p[NN*HH], g_h2pT[NN*HH];
__device__ float g_als1[NN], g_ald1[NN], g_als2[NN], g_ald2[NN];
__device__ float g_dinv[NN], g_selfe1[NN], g_selfe2[NN];
__device__ float g_rs1[NN], g_rs2[NN];
__device__ float g_va2[HH], g_vb2[HH];
__device__ float g_ewmean, g_c1, g_c2;

__device__ int g_off_a[NN+1], g_off_d[NN+1];
__device__ int g_tkt_a[NN], g_tkt_d[NN];
__device__ __align__(8) float2 g_pk_a[EE];
__device__ __align__(8) float2 g_pk_d1[EE];
__device__ __align__(8) float2 g_pk_d2[EE];
__device__ int g_dst_d[EE];
__device__ float g_ewp[EE];

// barrier state (monotonic generation; replay-safe)
__device__ unsigned g_arrive = 0;
__device__ unsigned g_gen = 0;

__device__ __forceinline__ void gsync(){
    __syncthreads();
    if (threadIdx.x == 0){
        unsigned gen = *(volatile unsigned*)&g_gen;
        __threadfence();
        if (atomicAdd(&g_arrive, 1u) == gridDim.x - 1){
            atomicExch(&g_arrive, 0u);
            __threadfence();
            atomicAdd(&g_gen, 1u);
        } else {
            while (*(volatile unsigned*)&g_gen == gen) { }
        }
    }
    __syncthreads();
}

// ---------------- helpers ----------------
__device__ __forceinline__ float lrelu(float v){ return v > 0.f ? v : 0.2f*v; }
__device__ __forceinline__ ull f2add(ull a, ull b){
    ull r; asm("add.rn.f32x2 %0, %1, %2;" : "=l"(r) : "l"(a), "l"(b)); return r; }
__device__ __forceinline__ ull f2fma(ull a, ull b, ull c){
    ull r; asm("fma.rn.f32x2 %0, %1, %2, %3;" : "=l"(r) : "l"(a), "l"(b), "l"(c)); return r; }
__device__ __forceinline__ float f2lo(ull v){ return __uint_as_float((unsigned)v); }
__device__ __forceinline__ float f2hi(ull v){ return __uint_as_float((unsigned)(v >> 32)); }
__device__ __forceinline__ ull fdup(float f){ ull u = __float_as_uint(f); return u | (u << 32); }
__device__ __forceinline__ ull fpack(float lo, float hi){
    return (ull)__float_as_uint(lo) | ((ull)__float_as_uint(hi) << 32); }

// ---------------- 16-node GEMM tile (512 thr: col=t&63, rg=t>>6 -> 2 rows) ----------------
template<int K, class L>
__device__ __forceinline__ void load_tile16(float* xs, int n0, const L& ld){
    const int LD = K + 4;
    for (int idx = threadIdx.x; idx < 16*K; idx += NT){
        int ln = idx / K, k = idx - ln*K;
        xs[ln*LD + k] = ld(n0 + ln, k);
    }
    __syncthreads();
}

template<int K>
__device__ __forceinline__ void compute_tile16(const float* xs, const float* __restrict__ W,
                                               int col, int rg, float acc[2]){
    const int LD = K + 4;
    const float* x0 = xs + rg*2*LD;
    acc[0]=0.f; acc[1]=0.f;
    #pragma unroll
    for (int k = 0; k < K; k += 4){
        float w0 = __ldg(W + (k+0)*64 + col);
        float w1 = __ldg(W + (k+1)*64 + col);
        float w2 = __ldg(W + (k+2)*64 + col);
        float w3 = __ldg(W + (k+3)*64 + col);
        #pragma unroll
        for (int i = 0; i < 2; i++){
            const float4 xv = *reinterpret_cast<const float4*>(x0 + i*LD + k);
            acc[i] = fmaf(xv.x, w0, acc[i]);
            acc[i] = fmaf(xv.y, w1, acc[i]);
            acc[i] = fmaf(xv.z, w2, acc[i]);
            acc[i] = fmaf(xv.w, w3, acc[i]);
        }
    }
}

struct LdRaw128 { const float* x;
    __device__ float operator()(int n, int k) const { return x[n*128 + k]; } };

// dual weighted row-reduction (P0 GEMM1a epilogue)
__device__ __forceinline__ void reduce_rows_dual(float a0, float a1, float wA, float wB,
                                                 float* outA, float* outB, int n0, float* sred){
    int t = threadIdx.x;
    if (t < 32) sred[t] = 0.f;
    __syncthreads();
    float pA0=a0*wA, pA1=a1*wA, pB0=a0*wB, pB1=a1*wB;
    #pragma unroll
    for (int o = 16; o > 0; o >>= 1){
        pA0 += __shfl_down_sync(0xffffffffu, pA0, o);
        pA1 += __shfl_down_sync(0xffffffffu, pA1, o);
        pB0 += __shfl_down_sync(0xffffffffu, pB0, o);
        pB1 += __shfl_down_sync(0xffffffffu, pB1, o);
    }
    if ((t & 31) == 0){
        int rg = t >> 6;
        atomicAdd(&sred[rg*2+0], pA0);
        atomicAdd(&sred[rg*2+1], pA1);
        atomicAdd(&sred[16+rg*2+0], pB0);
        atomicAdd(&sred[16+rg*2+1], pB1);
    }
    __syncthreads();
    if (t < 16) outA[n0+t] = sred[t];
    else if (t < 32) outB[n0+t-16] = sred[t];
}

// ---------------- gathers -> SMEM row; warp per node; lane = part*16 + col4 ----------------
__device__ __forceinline__ void gather_gcn_s(const float* __restrict__ h, const float* __restrict__ bias,
                                             float* __restrict__ smrow, int node){
    int lane = threadIdx.x & 31;
    int col4 = lane & 15, part = lane >> 4;
    const float2* __restrict__ pk = g_pk_a;
    int beg = g_off_a[node], end = g_off_a[node+1];
    float4 acc = make_float4(0.f,0.f,0.f,0.f);
    int i = beg + part;
    for (; i + 6 < end; i += 8){
        float2 q0 = __ldg(pk+i),   q1 = __ldg(pk+i+2);
        float2 q2 = __ldg(pk+i+4), q3 = __ldg(pk+i+6);
        int s0=__float_as_int(q0.y), s1=__float_as_int(q1.y);
        int s2=__float_as_int(q2.y), s3=__float_as_int(q3.y);
        float4 h0 = *(const float4*)(h + s0*64 + col4*4);
        float4 h1 = *(const float4*)(h + s1*64 + col4*4);
        float4 h2 = *(const float4*)(h + s2*64 + col4*4);
        float4 h3 = *(const float4*)(h + s3*64 + col4*4);
        acc.x = fmaf(q0.x,h0.x, fmaf(q1.x,h1.x, fmaf(q2.x,h2.x, fmaf(q3.x,h3.x, acc.x))));
        acc.y = fmaf(q0.x,h0.y, fmaf(q1.x,h1.y, fmaf(q2.x,h2.y, fmaf(q3.x,h3.y, acc.y))));
        acc.z = fmaf(q0.x,h0.z, fmaf(q1.x,h1.z, fmaf(q2.x,h2.z, fmaf(q3.x,h3.z, acc.z))));
        acc.w = fmaf(q0.x,h0.w, fmaf(q1.x,h1.w, fmaf(q2.x,h2.w, fmaf(q3.x,h3.w, acc.w))));
    }
    for (; i < end; i += 2){
        float2 q = __ldg(pk+i);
        int s = __float_as_int(q.y);
        float4 hv = *(const float4*)(h + s*64 + col4*4);
        acc.x = fmaf(q.x,hv.x,acc.x); acc.y = fmaf(q.x,hv.y,acc.y);
        acc.z = fmaf(q.x,hv.z,acc.z); acc.w = fmaf(q.x,hv.w,acc.w);
    }
    acc.x += __shfl_xor_sync(0xffffffffu, acc.x, 16);
    acc.y += __shfl_xor_sync(0xffffffffu, acc.y, 16);
    acc.z += __shfl_xor_sync(0xffffffffu, acc.z, 16);
    acc.w += __shfl_xor_sync(0xffffffffu, acc.w, 16);
    if (part == 0){
        float dd = g_dinv[node];
        float4 hs = *(const float4*)(h + node*64 + col4*4);
        float4 bb = *(const float4*)(bias + col4*4);
        float4 o;
        o.x = fmaxf(fmaf(dd, fmaf(dd, hs.x, acc.x), bb.x), 0.f);
        o.y = fmaxf(fmaf(dd, fmaf(dd, hs.y, acc.y), bb.y), 0.f);
        o.z = fmaxf(fmaf(dd, fmaf(dd, hs.z, acc.z), bb.z), 0.f);
        o.w = fmaxf(fmaf(dd, fmaf(dd, hs.w, acc.w), bb.w), 0.f);
        *(float4*)(smrow + col4*4) = o;
    }
}

template<bool EPI>
__device__ __forceinline__ void gather_gat_s(const float* __restrict__ h, const float2* __restrict__ pk,
                                             const float* __restrict__ selfe, const float* __restrict__ bias,
                                             float* __restrict__ smrow, int node){
    int lane = threadIdx.x & 31;
    int col4 = lane & 15, part = lane >> 4;
    int beg = g_off_d[node], end = g_off_d[node+1];
    float4 acc = make_float4(0.f,0.f,0.f,0.f);
    float den = 0.f;
    int i = beg + part;
    for (; i + 6 < end; i += 8){
        float2 q0 = __ldg(pk+i),   q1 = __ldg(pk+i+2);
        float2 q2 = __ldg(pk+i+4), q3 = __ldg(pk+i+6);
        int s0=__float_as_int(q0.y), s1=__float_as_int(q1.y);
        int s2=__float_as_int(q2.y), s3=__float_as_int(q3.y);
        float4 h0 = *(const float4*)(h + s0*64 + col4*4);
        float4 h1 = *(const float4*)(h + s1*64 + col4*4);
        float4 h2 = *(const float4*)(h + s2*64 + col4*4);
        float4 h3 = *(const float4*)(h + s3*64 + col4*4);
        den += (q0.x+q1.x)+(q2.x+q3.x);
        acc.x = fmaf(q0.x,h0.x, fmaf(q1.x,h1.x, fmaf(q2.x,h2.x, fmaf(q3.x,h3.x, acc.x))));
        acc.y = fmaf(q0.x,h0.y, fmaf(q1.x,h1.y, fmaf(q2.x,h2.y, fmaf(q3.x,h3.y, acc.y))));
        acc.z = fmaf(q0.x,h0.z, fmaf(q1.x,h1.z, fmaf(q2.x,h2.z, fmaf(q3.x,h3.z, acc.z))));
        acc.w = fmaf(q0.x,h0.w, fmaf(q1.x,h1.w, fmaf(q2.x,h2.w, fmaf(q3.x,h3.w, acc.w))));
    }
    for (; i < end; i += 2){
        float2 q = __ldg(pk+i);
        int s = __float_as_int(q.y);
        float4 hv = *(const float4*)(h + s*64 + col4*4);
        den += q.x;
        acc.x = fmaf(q.x,hv.x,acc.x); acc.y = fmaf(q.x,hv.y,acc.y);
        acc.z = fmaf(q.x,hv.z,acc.z); acc.w = fmaf(q.x,hv.w,acc.w);
    }
    acc.x += __shfl_xor_sync(0xffffffffu, acc.x, 16);
    acc.y += __shfl_xor_sync(0xffffffffu, acc.y, 16);
    acc.z += __shfl_xor_sync(0xffffffffu, acc.z, 16);
    acc.w += __shfl_xor_sync(0xffffffffu, acc.w, 16);
    den   += __shfl_xor_sync(0xffffffffu, den, 16);
    if (part == 0){
        float es = selfe[node];
        float inv = 1.0f / (den + es);
        float4 hs = *(const float4*)(h + node*64 + col4*4);
        float4 bb = *(const float4*)(bias + col4*4);
        float4 o;
        o.x = fmaxf(fmaf(es, hs.x, acc.x)*inv + bb.x, 0.f);
        o.y = fmaxf(fmaf(es, hs.y, acc.y)*inv + bb.y, 0.f);
        o.z = fmaxf(fmaf(es, hs.z, acc.z)*inv + bb.z, 0.f);
        o.w = fmaxf(fmaf(es, hs.w, acc.w)*inv + bb.w, 0.f);
        *(float4*)(smrow + col4*4) = o;
        if (EPI){
            int c0 = col4*4;
            float pa = o.x*g_va2[c0] + o.y*g_va2[c0+1] + o.z*g_va2[c0+2] + o.w*g_va2[c0+3];
            float pb = o.x*g_vb2[c0] + o.y*g_vb2[c0+1] + o.z*g_vb2[c0+2] + o.w*g_vb2[c0+3];
            #pragma unroll
            for (int off = 8; off > 0; off >>= 1){
                pa += __shfl_down_sync(0x0000FFFFu, pa, off);
                pb += __shfl_down_sync(0x0000FFFFu, pb, off);
            }
            if (col4 == 0){ g_als2[node] = pa; g_ald2[node] = pb; }
        }
    }
}

// ---------------- the single persistent kernel ----------------
__global__ void __launch_bounds__(NT, 1) kmain(
    const float* __restrict__ x, const int* __restrict__ eia, const int* __restrict__ eid,
    const float* __restrict__ ew,
    const float* __restrict__ Wg1, const float* __restrict__ bg1,
    const float* __restrict__ Wa1, const float* __restrict__ as1, const float* __restrict__ ad1,
    const float* __restrict__ we1, const float* __restrict__ ae1, const float* __restrict__ bgat1,
    const float* __restrict__ Wg2, const float* __restrict__ bg2,
    const float* __restrict__ Wa2, const float* __restrict__ as2, const float* __restrict__ ad2,
    const float* __restrict__ we2, const float* __restrict__ ae2, const float* __restrict__ bgat2,
    const float* __restrict__ Wg3, const float* __restrict__ bg3,
    const float* __restrict__ Wp1, const float* __restrict__ bp1,
    const float* __restrict__ Wp2, const float* __restrict__ bp2,
    float* __restrict__ out)
{
    extern __shared__ __align__(16) char sm[];
    int vb = blockIdx.x;
    int t = threadIdx.x;
    int wid = t >> 5;

    // ===== P0: GEMM1 (0-63 Wg, 64-127 Wa+attn) | hist+scan (128,129) | scalars (130) =====
    if (vb < 64){
        float* xs = (float*)sm;
        int n0 = vb*16;
        load_tile16<128>(xs, n0, LdRaw128{x});
        int col = t & 63, rg = t >> 6;
        float acc[2];
        compute_tile16<128>(xs, Wg1, col, rg, acc);
        #pragma unroll
        for (int i = 0; i < 2; i++) g_hg1[(n0 + rg*2 + i)*64 + col] = acc[i];
    } else if (vb < 128){
        float* xs = (float*)sm;
        float* sred = (float*)(sm + 8448);
        int n0 = (vb-64)*16;
        load_tile16<128>(xs, n0, LdRaw128{x});
        int col = t & 63, rg = t >> 6;
        float acc[2];
        compute_tile16<128>(xs, Wa1, col, rg, acc);
        #pragma unroll
        for (int i = 0; i < 2; i++) g_ha1[(n0 + rg*2 + i)*64 + col] = acc[i];
        reduce_rows_dual(acc[0], acc[1], as1[col], ad1[col], g_als1, g_ald1, n0, sred);
    } else if (vb < 130){
        // full hist + scan for one graph in a single block
        int g = vb - 128;
        int* hist = (int*)sm;            // [1024]
        int* tsm  = ((int*)sm) + NN;     // [256]
        for (int i = t; i < NN; i += NT) hist[i] = 0;
        __syncthreads();
        const int* dst = (g ? eid : eia) + EE;
        #pragma unroll
        for (int it = 0; it < EE/NT; it++) atomicAdd(&hist[dst[it*NT + t]], 1);
        __syncthreads();
        int v0=0,v1=0,v2=0,v3=0,local=0;
        if (t < 256){
            int base = t*4;
            const int4 q = *reinterpret_cast<const int4*>(&hist[base]);
            v0=q.x; v1=q.y; v2=q.z; v3=q.w;
            local = v0+v1+v2+v3;
            tsm[t] = local;
        }
        __syncthreads();
        for (int o = 1; o < 256; o <<= 1){
            int add = (t >= o && t < 256) ? tsm[t-o] : 0;
            __syncthreads();
            if (t < 256) tsm[t] += add;
            __syncthreads();
        }
        if (t < 256){
            int excl = tsm[t] - local;
            int base = t*4;
            int o0 = excl, o1 = o0+v0, o2 = o1+v1, o3 = o2+v2;
            int* off = g ? g_off_d : g_off_a;
            int* tkt = g ? g_tkt_d : g_tkt_a;
            off[base]=o0; off[base+1]=o1; off[base+2]=o2; off[base+3]=o3;
            tkt[base]=o0; tkt[base+1]=o1; tkt[base+2]=o2; tkt[base+3]=o3;
            if (t == 255) off[NN] = o3 + v3;
            if (g == 0){
                g_dinv[base+0] = rsqrtf((float)(v0+1));
                g_dinv[base+1] = rsqrtf((float)(v1+1));
                g_dinv[base+2] = rsqrtf((float)(v2+1));
                g_dinv[base+3] = rsqrtf((float)(v3+1));
            }
        }
    } else if (vb == 130){
        float* sr = (float*)sm;
        float s = 0.f;
        for (int i = t; i < EE; i += NT) s += ew[i];
        sr[t] = s; __syncthreads();
        for (int o = 256; o > 0; o >>= 1){ if (t < o) sr[t] += sr[t+o]; __syncthreads(); }
        if (t == 0) g_ewmean = sr[0] * (1.0f/EE);
        __syncthreads();
        sr[t] = (t < 64) ? we1[t]*ae1[t] : 0.f; __syncthreads();
        for (int o = 256; o > 0; o >>= 1){ if (t < o) sr[t] += sr[t+o]; __syncthreads(); }
        if (t == 0) g_c1 = sr[0];
        __syncthreads();
        sr[t] = (t < 64) ? we2[t]*ae2[t] : 0.f; __syncthreads();
        for (int o = 256; o > 0; o >>= 1){ if (t < o) sr[t] += sr[t+o]; __syncthreads(); }
        if (t == 0) g_c2 = sr[0];
        if (t < 64){
            float pa = 0.f, pb = 0.f;
            #pragma unroll 8
            for (int c = 0; c < 64; c++){
                float w = Wa2[t*64 + c];
                pa = fmaf(w, as2[c], pa);
                pb = fmaf(w, ad2[c], pb);
            }
            g_va2[t] = pa; g_vb2[t] = pb;
        }
    }
    gsync();

    // ===== P1: fill A (0-31) | fill/pack D (32-63) | selfe1 (64,65) =====
    if (vb < 32){
        int e = vb*NT + t;
        int s = eia[e], d = eia[EE + e];
        int pos = atomicAdd(&g_tkt_a[d], 1);
        g_pk_a[pos] = make_float2(g_dinv[s], __int_as_float(s));
    } else if (vb < 64){
        int e = (vb-32)*NT + t;
        int s = eid[e], d = eid[EE + e];
        float w = ew[e];
        int pos = atomicAdd(&g_tkt_d[d], 1);
        g_pk_d1[pos] = make_float2(__expf(lrelu(g_als1[s] + g_ald1[d] + w*g_c1)),
                                   __int_as_float(s));
        g_dst_d[pos] = d;
        g_ewp[pos] = w;
    } else if (vb < 66){
        int n = (vb-64)*NT + t;
        g_selfe1[n] = __expf(lrelu(g_als1[n] + g_ald1[n] + g_ewmean*g_c1));
    }
    gsync();

    // ===== P2: fused gather1 + GEMM2 (A: 0-63, D: 64-127) =====
    if (vb < 64){
        float* xs = (float*)sm;                    // 16 x 68
        int n0 = vb*16;
        gather_gcn_s(g_hg1, bg1, xs + wid*68, n0 + wid);
        __syncthreads();
        int col = t & 63, rg = t >> 6;
        float acc[2];
        compute_tile16<64>(xs, Wg2, col, rg, acc);
        #pragma unroll
        for (int i = 0; i < 2; i++) g_hg2[(n0 + rg*2 + i)*64 + col] = acc[i];
    } else if (vb < 128){
        float* xs = (float*)sm;
        int n0 = (vb-64)*16;
        gather_gat_s<true>(g_ha1, g_pk_d1, g_selfe1, bgat1, xs + wid*68, n0 + wid);
        __syncthreads();
        int col = t & 63, rg = t >> 6;
        float acc[2];
        compute_tile16<64>(xs, Wa2, col, rg, acc);
        #pragma unroll
        for (int i = 0; i < 2; i++) g_ha2[(n0 + rg*2 + i)*64 + col] = acc[i];
    }
    gsync();

    // ===== P3: pack w2 (0-31) | selfe2 (32,33) =====
    if (vb < 32){
        int p = vb*NT + t;
        float2 q = g_pk_d1[p];
        int s = __float_as_int(q.y);
        int d = g_dst_d[p];
        g_pk_d2[p] = make_float2(__expf(lrelu(g_als2[s] + g_ald2[d] + g_ewp[p]*g_c2)), q.y);
    } else if (vb < 34){
        int n = (vb-32)*NT + t;
        g_selfe2[n] = __expf(lrelu(g_als2[n] + g_ald2[n] + g_ewmean*g_c2));
    }
    gsync();

    // ===== P4: fused gather2 (GCN+GAT) + mix + GEMM3 (0-127, 8 nodes each) =====
    if (vb < 128){
        float* smA = (float*)sm;           // 8 x 68
        float* smB = smA + 8*68;           // 8 x 68
        int n0 = vb*8;
        if (wid < 8) gather_gcn_s(g_hg2, bg2, smA + wid*68, n0 + wid);
        else         gather_gat_s<false>(g_ha2, g_pk_d2, g_selfe2, bgat2,
                                         smB + (wid-8)*68, n0 + (wid-8));
        __syncthreads();
        {   // mix in place: 512 elems
            int r = t >> 6, c = t & 63;
            smA[r*68 + c] = 0.7f*smA[r*68 + c] + 0.3f*smB[r*68 + c];
        }
        __syncthreads();
        int col = t & 63, row = t >> 6;
        float acc = 0.f;
        #pragma unroll
        for (int k = 0; k < 64; k += 4){
            float w0 = __ldg(Wg3 + (k+0)*64 + col);
            float w1 = __ldg(Wg3 + (k+1)*64 + col);
            float w2 = __ldg(Wg3 + (k+2)*64 + col);
            float w3 = __ldg(Wg3 + (k+3)*64 + col);
            const float4 xv = *reinterpret_cast<const float4*>(smA + row*68 + k);
            acc = fmaf(xv.x, w0, acc);
            acc = fmaf(xv.y, w1, acc);
            acc = fmaf(xv.z, w2, acc);
            acc = fmaf(xv.w, w3, acc);
        }
        g_hg3[(n0 + row)*64 + col] = acc;
    }
    gsync();

    // ===== P5: fused gather3 + predictor GEMM + rowsums (0-127, 8 nodes each) =====
    if (vb < 128){
        float* smH = (float*)sm;            // 8 x 68
        float* sred = smH + 8*68;           // 16 floats
        int n0 = vb*8;
        if (wid < 8) gather_gcn_s(g_hg3, bg3, smH + wid*68, n0 + wid);
        if (t < 16) sred[t] = 0.f;
        __syncthreads();
        int col = t & 127, rg = t >> 7;     // rows rg, rg+4
        bool hi = col >= 64;
        const float* Wbase = hi ? (Wp1 + 64*64 + (col-64)) : (Wp1 + col);
        float acc0 = 0.f, acc1 = 0.f;
        #pragma unroll
        for (int k = 0; k < 64; k += 2){
            float w0 = __ldg(Wbase + (k+0)*64);
            float w1 = __ldg(Wbase + (k+1)*64);
            float a0 = smH[rg*68 + k],     a1 = smH[rg*68 + k + 1];
            float b0 = smH[(rg+4)*68 + k], b1 = smH[(rg+4)*68 + k + 1];
            acc0 = fmaf(a0, w0, acc0); acc0 = fmaf(a1, w1, acc0);
            acc1 = fmaf(b0, w0, acc1); acc1 = fmaf(b1, w1, acc1);
        }
        float wp2 = __ldg(Wp2 + (col & 63));
        if (!hi){
            float bb = __ldg(bp1 + col);
            acc0 += bb; acc1 += bb;
            g_h1p[(n0 + rg)*64 + col] = acc0;
            g_h1p[(n0 + rg + 4)*64 + col] = acc1;
        } else {
            g_h2pT[(col-64)*NN + n0 + rg] = acc0;
            g_h2pT[(col-64)*NN + n0 + rg + 4] = acc1;
        }
        float p0 = acc0*wp2, p1 = acc1*wp2;
        #pragma unroll
        for (int o = 16; o > 0; o >>= 1){
            p0 += __shfl_down_sync(0xffffffffu, p0, o);
            p1 += __shfl_down_sync(0xffffffffu, p1, o);
        }
        if ((t & 31) == 0){
            int base = hi ? 8 : 0;
            atomicAdd(&sred[base + rg], p0);
            atomicAdd(&sred[base + rg + 4], p1);
        }
        __syncthreads();
        if (t < 8) g_rs1[n0 + t] = sred[t];
        else if (t < 16) g_rs2[n0 + t - 8] = sred[t];
    }
    gsync();

    // ===== P6: all-pairs predictor, 64x128 tiles (0-127) =====
    if (vb < 128){
        ull* s1d  = (ull*)sm;                        // [64][65] dup pairs   (33280B)
        ull* s2a  = (ull*)(sm + 33280);              // [64][33] cols 0,1 mod4 (16896B)
        ull* s2b  = (ull*)(sm + 33280 + 16896);      // [64][33] cols 2,3 mod4 (16896B)
        ull* swpd = (ull*)(sm + 33280 + 33792);      // [64] dup 0.5*w       (512B)
        int bi = vb >> 3, bj = vb & 7;
        int i0 = bi*64, j0 = bj*128;
        for (int i = t; i < 1024; i += NT){
            int row = i >> 4, seg = (i & 15)*4;
            float4 v = *(const float4*)(g_h1p + (i0+row)*64 + seg);
            ull* d = s1d + row*65 + seg;
            d[0] = fdup(v.x); d[1] = fdup(v.y); d[2] = fdup(v.z); d[3] = fdup(v.w);
        }
        for (int i = t; i < 2048; i += NT){
            int h = i >> 5, j4 = i & 31;
            float4 v = *(const float4*)(g_h2pT + h*NN + j0 + j4*4);
            s2a[h*33 + j4] = fpack(v.x, v.y);
            s2b[h*33 + j4] = fpack(v.z, v.w);
        }
        if (t < 64) swpd[t] = fdup(0.5f*__ldg(Wp2 + t));
        __syncthreads();

        int tx = t & 31, ty = t >> 5;
        const ull ABS2 = 0x7FFFFFFF7FFFFFFFULL;
        ull acc[4][2];
        #pragma unroll
        for (int a = 0; a < 4; a++){ acc[a][0] = 0ULL; acc[a][1] = 0ULL; }
        const ull* s1p = s1d + (ty*4)*65;

        #pragma unroll 8
        for (int h = 0; h < 64; h++){
            ull w2 = swpd[h];
            ull r2a = s2a[h*33 + tx];
            ull r2b = s2b[h*33 + tx];
            #pragma unroll
            for (int a = 0; a < 4; a++){
                ull r1 = s1p[a*65 + h];
                ull t0 = f2add(r1, r2a) & ABS2;
                ull t1 = f2add(r1, r2b) & ABS2;
                acc[a][0] = f2fma(t0, w2, acc[a][0]);
                acc[a][1] = f2fma(t1, w2, acc[a][1]);
            }
        }
        float bb = bp2[0];
        float hr2[4];
        #pragma unroll
        for (int c = 0; c < 4; c++) hr2[c] = 0.5f*__ldg(g_rs2 + j0 + tx*4 + c);
        #pragma unroll
        for (int a = 0; a < 4; a++){
            int row = i0 + ty*4 + a;
            float base = 0.5f*__ldg(g_rs1 + row) + bb;
            float l0 = f2lo(acc[a][0]) + base + hr2[0];
            float l1 = f2hi(acc[a][0]) + base + hr2[1];
            float l2 = f2lo(acc[a][1]) + base + hr2[2];
            float l3 = f2hi(acc[a][1]) + base + hr2[3];
            float4 o;
            o.x = 1.0f / (1.0f + __expf(-l0));
            o.y = 1.0f / (1.0f + __expf(-l1));
            o.z = 1.0f / (1.0f + __expf(-l2));
            o.w = 1.0f / (1.0f + __expf(-l3));
            *reinterpret_cast<float4*>(out + row*NN + j0 + tx*4) = o;
        }
    }
}

// ---------------- launch ----------------
extern "C" void kernel_launch(void* const* d_in, const int* in_sizes, int n_in,
                              void* d_out, int out_size){
    const float* x    = (const float*)d_in[0];
    const int*   eia  = (const int*)  d_in[1];
    const int*   eid  = (const int*)  d_in[2];
    const float* ew   = (const float*)d_in[3];
    const float* Wg1  = (const float*)d_in[4];
    const float* bg1  = (const float*)d_in[5];
    const float* Wa1  = (const float*)d_in[6];
    const float* as1  = (const float*)d_in[7];
    const float* ad1  = (const float*)d_in[8];
    const float* we1  = (const float*)d_in[9];
    const float* ae1  = (const float*)d_in[10];
    const float* bgat1= (const float*)d_in[11];
    const float* Wg2  = (const float*)d_in[12];
    const float* bg2  = (const float*)d_in[13];
    const float* Wa2  = (const float*)d_in[14];
    const float* as2  = (const float*)d_in[15];
    const float* ad2  = (const float*)d_in[16];
    const float* we2  = (const float*)d_in[17];
    const float* ae2  = (const float*)d_in[18];
    const float* bgat2= (const float*)d_in[19];
    const float* Wg3  = (const float*)d_in[20];
    const float* bg3  = (const float*)d_in[21];
    const float* Wp1  = (const float*)d_in[22];
    const float* bp1  = (const float*)d_in[23];
    const float* Wp2  = (const float*)d_in[24];
    const float* bp2  = (const float*)d_in[25];
    float* out = (float*)d_out;

    const int smem = 33280 + 33792 + 512;   // 67584 bytes (P6 layout is max)
    static int s_attr_done = 0;
    if (!s_attr_done){
        cudaFuncSetAttribute(kmain, cudaFuncAttributeMaxDynamicSharedMemorySize, smem);
        s_attr_done = 1;
    }

    kmain<<<NB, NT, smem>>>(x, eia, eid, ew,
                            Wg1, bg1, Wa1, as1, ad1, we1, ae1, bgat1,
                            Wg2, bg2, Wa2, as2, ad2, we2, ae2, bgat2,
                            Wg3, bg3, Wp1, bp1, Wp2, bp2, out);
}

// round 6
// speedup vs baseline: 1.6988x; 1.1436x over previous
#include <cuda_runtime.h>
#include <cuda_bf16.h>

#define NN 1024
#define HH 64
#define EE 16384
#define NB 148
#define NT 512
#define SLOTS 64

typedef unsigned long long ull;

// ---------------- scratch (device globals; no allocation) ----------------
__device__ __align__(16) float g_hg1[NN*HH], g_ha1[NN*HH], g_hg2[NN*HH], g_ha2[NN*HH], g_hg3[NN*HH];
__device__ __align__(16) float g_h1p[NN*HH], g_h2pT[NN*HH];
__device__ float g_als1[NN], g_ald1[NN], g_als2[NN], g_ald2[NN];
__device__ float g_rs1[NN], g_rs2[NN];
__device__ float g_va2[HH], g_vb2[HH];
__device__ float g_ewmean, g_c1, g_c2;

// bucketed adjacency (dst-major, fixed stride), rebuilt each launch
__device__ int g_cnt_a[NN], g_cnt_d[NN];      // zeroed at load; re-zeroed in P4
__device__ int g_sa[NN*SLOTS];                 // graph A: src per slot
__device__ __align__(8) float2 g_sd[NN*SLOTS]; // graph D: (ew, src-bits) per slot

// barrier state (monotonic generation; replay-safe)
__device__ unsigned g_arrive = 0;
__device__ unsigned g_gen = 0;

__device__ __forceinline__ void gsync(){
    __syncthreads();
    if (threadIdx.x == 0){
        unsigned gen = *(volatile unsigned*)&g_gen;
        __threadfence();
        if (atomicAdd(&g_arrive, 1u) == gridDim.x - 1){
            atomicExch(&g_arrive, 0u);
            __threadfence();
            atomicAdd(&g_gen, 1u);
        } else {
            while (*(volatile unsigned*)&g_gen == gen) { }
        }
    }
    __syncthreads();
}

// ---------------- helpers ----------------
__device__ __forceinline__ float lrelu(float v){ return v > 0.f ? v : 0.2f*v; }
__device__ __forceinline__ ull f2add(ull a, ull b){
    ull r; asm("add.rn.f32x2 %0, %1, %2;" : "=l"(r) : "l"(a), "l"(b)); return r; }
__device__ __forceinline__ ull f2fma(ull a, ull b, ull c){
    ull r; asm("fma.rn.f32x2 %0, %1, %2, %3;" : "=l"(r) : "l"(a), "l"(b), "l"(c)); return r; }
__device__ __forceinline__ float f2lo(ull v){ return __uint_as_float((unsigned)v); }
__device__ __forceinline__ float f2hi(ull v){ return __uint_as_float((unsigned)(v >> 32)); }
__device__ __forceinline__ ull fdup(float f){ ull u = __float_as_uint(f); return u | (u << 32); }
__device__ __forceinline__ ull fpack(float lo, float hi){
    return (ull)__float_as_uint(lo) | ((ull)__float_as_uint(hi) << 32); }

// ---------------- GEMM1: 32-node tile, K=128 (512 thr: col=t&63, rg=t>>6 -> 4 rows) ----------------
__device__ __forceinline__ void load_tile32_128(float* xs, int n0, const float* __restrict__ x){
    for (int idx = threadIdx.x; idx < 1024; idx += NT){
        int r = idx >> 5, c4 = idx & 31;
        float4 v = *(const float4*)(x + (n0+r)*128 + c4*4);
        *(float4*)(xs + r*132 + c4*4) = v;
    }
    __syncthreads();
}

__device__ __forceinline__ void compute_tile32_128(const float* xs, const float* __restrict__ W,
                                                   int col, int rg, float acc[4]){
    const int LD = 132;
    const float* x0 = xs + rg*4*LD;
    acc[0]=0.f; acc[1]=0.f; acc[2]=0.f; acc[3]=0.f;
    #pragma unroll
    for (int k = 0; k < 128; k += 4){
        float w0 = __ldg(W + (k+0)*64 + col);
        float w1 = __ldg(W + (k+1)*64 + col);
        float w2 = __ldg(W + (k+2)*64 + col);
        float w3 = __ldg(W + (k+3)*64 + col);
        #pragma unroll
        for (int i = 0; i < 4; i++){
            const float4 xv = *reinterpret_cast<const float4*>(x0 + i*LD + k);
            acc[i] = fmaf(xv.x, w0, acc[i]);
            acc[i] = fmaf(xv.y, w1, acc[i]);
            acc[i] = fmaf(xv.z, w2, acc[i]);
            acc[i] = fmaf(xv.w, w3, acc[i]);
        }
    }
}

// ---------------- GEMM2: 16-node tile, K=64 from smem rows LD=68 ----------------
__device__ __forceinline__ void compute_tile16_64(const float* xs, const float* __restrict__ W,
                                                  int col, int rg, float acc[2]){
    const int LD = 68;
    const float* x0 = xs + rg*2*LD;
    acc[0]=0.f; acc[1]=0.f;
    #pragma unroll
    for (int k = 0; k < 64; k += 4){
        float w0 = __ldg(W + (k+0)*64 + col);
        float w1 = __ldg(W + (k+1)*64 + col);
        float w2 = __ldg(W + (k+2)*64 + col);
        float w3 = __ldg(W + (k+3)*64 + col);
        #pragma unroll
        for (int i = 0; i < 2; i++){
            const float4 xv = *reinterpret_cast<const float4*>(x0 + i*LD + k);
            acc[i] = fmaf(xv.x, w0, acc[i]);
            acc[i] = fmaf(xv.y, w1, acc[i]);
            acc[i] = fmaf(xv.z, w2, acc[i]);
            acc[i] = fmaf(xv.w, w3, acc[i]);
        }
    }
}

// ---------------- gathers (inline weights) -> SMEM row; warp per node ----------------
// GCN: weight = rsqrt(cntf[s]); epilogue dd = rsqrt(cntf[node])
__device__ __forceinline__ void gather_gcn_i(const float* __restrict__ h, const float* __restrict__ bias,
                                             const float* __restrict__ cntf,
                                             float* __restrict__ smrow, int node){
    int lane = threadIdx.x & 31;
    int col4 = lane & 15, part = lane >> 4;
    const int* __restrict__ sa = g_sa + node*SLOTS;
    int end = __float2int_rn(cntf[node]) - 1;
    float4 acc = make_float4(0.f,0.f,0.f,0.f);
    int i = part;
    for (; i + 6 < end; i += 8){
        int s0 = sa[i], s1 = sa[i+2], s2 = sa[i+4], s3 = sa[i+6];
        float4 h0 = *(const float4*)(h + s0*64 + col4*4);
        float4 h1 = *(const float4*)(h + s1*64 + col4*4);
        float4 h2 = *(const float4*)(h + s2*64 + col4*4);
        float4 h3 = *(const float4*)(h + s3*64 + col4*4);
        float w0 = rsqrtf(cntf[s0]);
        float w1 = rsqrtf(cntf[s1]);
        float w2 = rsqrtf(cntf[s2]);
        float w3 = rsqrtf(cntf[s3]);
        acc.x = fmaf(w0,h0.x, fmaf(w1,h1.x, fmaf(w2,h2.x, fmaf(w3,h3.x, acc.x))));
        acc.y = fmaf(w0,h0.y, fmaf(w1,h1.y, fmaf(w2,h2.y, fmaf(w3,h3.y, acc.y))));
        acc.z = fmaf(w0,h0.z, fmaf(w1,h1.z, fmaf(w2,h2.z, fmaf(w3,h3.z, acc.z))));
        acc.w = fmaf(w0,h0.w, fmaf(w1,h1.w, fmaf(w2,h2.w, fmaf(w3,h3.w, acc.w))));
    }
    for (; i < end; i += 2){
        int s = sa[i];
        float4 hv = *(const float4*)(h + s*64 + col4*4);
        float w = rsqrtf(cntf[s]);
        acc.x = fmaf(w,hv.x,acc.x); acc.y = fmaf(w,hv.y,acc.y);
        acc.z = fmaf(w,hv.z,acc.z); acc.w = fmaf(w,hv.w,acc.w);
    }
    acc.x += __shfl_xor_sync(0xffffffffu, acc.x, 16);
    acc.y += __shfl_xor_sync(0xffffffffu, acc.y, 16);
    acc.z += __shfl_xor_sync(0xffffffffu, acc.z, 16);
    acc.w += __shfl_xor_sync(0xffffffffu, acc.w, 16);
    if (part == 0){
        float dd = rsqrtf(cntf[node]);
        float4 hs = *(const float4*)(h + node*64 + col4*4);
        float4 bb = *(const float4*)(bias + col4*4);
        float4 o;
        o.x = fmaxf(fmaf(dd, fmaf(dd, hs.x, acc.x), bb.x), 0.f);
        o.y = fmaxf(fmaf(dd, fmaf(dd, hs.y, acc.y), bb.y), 0.f);
        o.z = fmaxf(fmaf(dd, fmaf(dd, hs.z, acc.z), bb.z), 0.f);
        o.w = fmaxf(fmaf(dd, fmaf(dd, hs.w, acc.w), bb.w), 0.f);
        *(float4*)(smrow + col4*4) = o;
    }
}

// GAT: weight = exp(lrelu(als[s] + ald[node] + ew*c)); self = exp(lrelu(als[n]+ald[n]+ewmean*c))
template<bool EPI>
__device__ __forceinline__ void gather_gat_i(const float* __restrict__ h,
                                             const float* __restrict__ als, const float* __restrict__ ald,
                                             float cc, const float* __restrict__ bias,
                                             float* __restrict__ smrow, int node){
    int lane = threadIdx.x & 31;
    int col4 = lane & 15, part = lane >> 4;
    const float2* __restrict__ sd = g_sd + node*SLOTS;
    int end = g_cnt_d[node];
    float aldd = ald[node];
    float4 acc = make_float4(0.f,0.f,0.f,0.f);
    float den = 0.f;
    int i = part;
    for (; i + 6 < end; i += 8){
        float2 q0 = sd[i], q1 = sd[i+2], q2 = sd[i+4], q3 = sd[i+6];
        int s0=__float_as_int(q0.y), s1=__float_as_int(q1.y);
        int s2=__float_as_int(q2.y), s3=__float_as_int(q3.y);
        float4 h0 = *(const float4*)(h + s0*64 + col4*4);
        float4 h1 = *(const float4*)(h + s1*64 + col4*4);
        float4 h2 = *(const float4*)(h + s2*64 + col4*4);
        float4 h3 = *(const float4*)(h + s3*64 + col4*4);
        float w0 = __expf(lrelu(als[s0] + aldd + q0.x*cc));
        float w1 = __expf(lrelu(als[s1] + aldd + q1.x*cc));
        float w2 = __expf(lrelu(als[s2] + aldd + q2.x*cc));
        float w3 = __expf(lrelu(als[s3] + aldd + q3.x*cc));
        den += (w0+w1)+(w2+w3);
        acc.x = fmaf(w0,h0.x, fmaf(w1,h1.x, fmaf(w2,h2.x, fmaf(w3,h3.x, acc.x))));
        acc.y = fmaf(w0,h0.y, fmaf(w1,h1.y, fmaf(w2,h2.y, fmaf(w3,h3.y, acc.y))));
        acc.z = fmaf(w0,h0.z, fmaf(w1,h1.z, fmaf(w2,h2.z, fmaf(w3,h3.z, acc.z))));
        acc.w = fmaf(w0,h0.w, fmaf(w1,h1.w, fmaf(w2,h2.w, fmaf(w3,h3.w, acc.w))));
    }
    for (; i < end; i += 2){
        float2 q = sd[i];
        int s = __float_as_int(q.y);
        float4 hv = *(const float4*)(h + s*64 + col4*4);
        float w = __expf(lrelu(als[s] + aldd + q.x*cc));
        den += w;
        acc.x = fmaf(w,hv.x,acc.x); acc.y = fmaf(w,hv.y,acc.y);
        acc.z = fmaf(w,hv.z,acc.z); acc.w = fmaf(w,hv.w,acc.w);
    }
    acc.x += __shfl_xor_sync(0xffffffffu, acc.x, 16);
    acc.y += __shfl_xor_sync(0xffffffffu, acc.y, 16);
    acc.z += __shfl_xor_sync(0xffffffffu, acc.z, 16);
    acc.w += __shfl_xor_sync(0xffffffffu, acc.w, 16);
    den   += __shfl_xor_sync(0xffffffffu, den, 16);
    if (part == 0){
        float es = __expf(lrelu(als[node] + aldd + g_ewmean*cc));
        float inv = 1.0f / (den + es);
        float4 hs = *(const float4*)(h + node*64 + col4*4);
        float4 bb = *(const float4*)(bias + col4*4);
        float4 o;
        o.x = fmaxf(fmaf(es, hs.x, acc.x)*inv + bb.x, 0.f);
        o.y = fmaxf(fmaf(es, hs.y, acc.y)*inv + bb.y, 0.f);
        o.z = fmaxf(fmaf(es, hs.z, acc.z)*inv + bb.z, 0.f);
        o.w = fmaxf(fmaf(es, hs.w, acc.w)*inv + bb.w, 0.f);
        *(float4*)(smrow + col4*4) = o;
        if (EPI){
            int c0 = col4*4;
            float pa = o.x*g_va2[c0] + o.y*g_va2[c0+1] + o.z*g_va2[c0+2] + o.w*g_va2[c0+3];
            float pb = o.x*g_vb2[c0] + o.y*g_vb2[c0+1] + o.z*g_vb2[c0+2] + o.w*g_vb2[c0+3];
            #pragma unroll
            for (int off = 8; off > 0; off >>= 1){
                pa += __shfl_down_sync(0x0000FFFFu, pa, off);
                pb += __shfl_down_sync(0x0000FFFFu, pb, off);
            }
            if (col4 == 0){ g_als2[node] = pa; g_ald2[node] = pb; }
        }
    }
}

// ---------------- the single persistent kernel ----------------
__global__ void __launch_bounds__(NT, 1) kmain(
    const float* __restrict__ x, const int* __restrict__ eia, const int* __restrict__ eid,
    const float* __restrict__ ew,
    const float* __restrict__ Wg1, const float* __restrict__ bg1,
    const float* __restrict__ Wa1, const float* __restrict__ as1, const float* __restrict__ ad1,
    const float* __restrict__ we1, const float* __restrict__ ae1, const float* __restrict__ bgat1,
    const float* __restrict__ Wg2, const float* __restrict__ bg2,
    const float* __restrict__ Wa2, const float* __restrict__ as2, const float* __restrict__ ad2,
    const float* __restrict__ we2, const float* __restrict__ ae2, const float* __restrict__ bgat2,
    const float* __restrict__ Wg3, const float* __restrict__ bg3,
    const float* __restrict__ Wp1, const float* __restrict__ bp1,
    const float* __restrict__ Wp2, const float* __restrict__ bp2,
    float* __restrict__ out)
{
    extern __shared__ __align__(16) char sm[];
    int vb = blockIdx.x;
    int t = threadIdx.x;
    int wid = t >> 5;

    // ===== P0: GEMM1 Wg (0-31) | GEMM1 Wa + attn (32-63) | fill A (64-79) | fill D (80-95) | scalars (96) =====
    if (vb < 32){
        float* xs = (float*)sm;                     // 32 x 132
        int n0 = vb*32;
        load_tile32_128(xs, n0, x);
        int col = t & 63, rg = t >> 6;
        float acc[4];
        compute_tile32_128(xs, Wg1, col, rg, acc);
        #pragma unroll
        for (int i = 0; i < 4; i++) g_hg1[(n0 + rg*4 + i)*64 + col] = acc[i];
    } else if (vb < 64){
        float* xs = (float*)sm;
        float* sred = (float*)(sm + 16896);         // 64 floats
        int n0 = (vb-32)*32;
        load_tile32_128(xs, n0, x);
        int col = t & 63, rg = t >> 6;
        float acc[4];
        compute_tile32_128(xs, Wa1, col, rg, acc);
        #pragma unroll
        for (int i = 0; i < 4; i++) g_ha1[(n0 + rg*4 + i)*64 + col] = acc[i];
        // attn epilogue: als1[n] = row.as1, ald1[n] = row.ad1
        if (t < 64) sred[t] = 0.f;
        __syncthreads();
        float wa = as1[col], wb = ad1[col];
        float p[4], q[4];
        #pragma unroll
        for (int i = 0; i < 4; i++){ p[i] = acc[i]*wa; q[i] = acc[i]*wb; }
        #pragma unroll
        for (int o = 16; o > 0; o >>= 1){
            #pragma unroll
            for (int i = 0; i < 4; i++){
                p[i] += __shfl_down_sync(0xffffffffu, p[i], o);
                q[i] += __shfl_down_sync(0xffffffffu, q[i], o);
            }
        }
        if ((t & 31) == 0){
            #pragma unroll
            for (int i = 0; i < 4; i++){
                atomicAdd(&sred[rg*4 + i], p[i]);
                atomicAdd(&sred[32 + rg*4 + i], q[i]);
            }
        }
        __syncthreads();
        if (t < 32) g_als1[n0 + t] = sred[t];
        else if (t < 64) g_ald1[n0 + t - 32] = sred[t];
    } else if (vb < 80){
        int f = vb - 64;
        #pragma unroll
        for (int r = 0; r < 2; r++){
            int e = f*1024 + r*NT + t;
            int s = eia[e], d = eia[EE + e];
            int pos = atomicAdd(&g_cnt_a[d], 1);
            if (pos < SLOTS) g_sa[d*SLOTS + pos] = s;
        }
    } else if (vb < 96){
        int f = vb - 80;
        #pragma unroll
        for (int r = 0; r < 2; r++){
            int e = f*1024 + r*NT + t;
            int s = eid[e], d = eid[EE + e];
            int pos = atomicAdd(&g_cnt_d[d], 1);
            if (pos < SLOTS) g_sd[d*SLOTS + pos] = make_float2(ew[e], __int_as_float(s));
        }
    } else if (vb == 96){
        float* sr = (float*)sm;
        float s = 0.f;
        for (int i = t; i < EE; i += NT) s += ew[i];
        sr[t] = s; __syncthreads();
        for (int o = 256; o > 0; o >>= 1){ if (t < o) sr[t] += sr[t+o]; __syncthreads(); }
        if (t == 0) g_ewmean = sr[0] * (1.0f/EE);
        __syncthreads();
        sr[t] = (t < 64) ? we1[t]*ae1[t] : 0.f; __syncthreads();
        for (int o = 256; o > 0; o >>= 1){ if (t < o) sr[t] += sr[t+o]; __syncthreads(); }
        if (t == 0) g_c1 = sr[0];
        __syncthreads();
        sr[t] = (t < 64) ? we2[t]*ae2[t] : 0.f; __syncthreads();
        for (int o = 256; o > 0; o >>= 1){ if (t < o) sr[t] += sr[t+o]; __syncthreads(); }
        if (t == 0) g_c2 = sr[0];
        if (t < 64){
            float pa = 0.f, pb = 0.f;
            #pragma unroll 8
            for (int c = 0; c < 64; c++){
                float w = Wa2[t*64 + c];
                pa = fmaf(w, as2[c], pa);
                pb = fmaf(w, ad2[c], pb);
            }
            g_va2[t] = pa; g_vb2[t] = pb;
        }
    }
    gsync();

    // ===== P1: fused gather1 + GEMM2 (GCN: 0-63, GAT: 64-127; 16 nodes each) =====
    if (vb < 64){
        float* cntf = (float*)sm;                   // 1024
        float* xs = (float*)(sm + 4096);            // 16 x 68
        for (int i = t; i < NN; i += NT) cntf[i] = (float)(g_cnt_a[i] + 1);
        __syncthreads();
        int n0 = vb*16;
        gather_gcn_i(g_hg1, bg1, cntf, xs + wid*68, n0 + wid);
        __syncthreads();
        int col = t & 63, rg = t >> 6;
        float acc[2];
        compute_tile16_64(xs, Wg2, col, rg, acc);
        #pragma unroll
        for (int i = 0; i < 2; i++) g_hg2[(n0 + rg*2 + i)*64 + col] = acc[i];
    } else if (vb < 128){
        float* als = (float*)sm;                    // 1024
        float* ald = (float*)(sm + 4096);           // 1024
        float* xs  = (float*)(sm + 8192);           // 16 x 68
        for (int i = t; i < NN; i += NT){ als[i] = g_als1[i]; ald[i] = g_ald1[i]; }
        __syncthreads();
        int n0 = (vb-64)*16;
        gather_gat_i<true>(g_ha1, als, ald, g_c1, bgat1, xs + wid*68, n0 + wid);
        __syncthreads();
        int col = t & 63, rg = t >> 6;
        float acc[2];
        compute_tile16_64(xs, Wa2, col, rg, acc);
        #pragma unroll
        for (int i = 0; i < 2; i++) g_ha2[(n0 + rg*2 + i)*64 + col] = acc[i];
    }
    gsync();

    // ===== P2: fused gather2 (GCN+GAT) + mix + GEMM3 (0-127, 8 nodes each) =====
    if (vb < 128){
        float* cntf = (float*)sm;                   // 1024
        float* als2 = (float*)(sm + 4096);          // 1024
        float* ald2 = (float*)(sm + 8192);          // 1024
        float* smA  = (float*)(sm + 12288);         // 8 x 68
        float* smB  = smA + 8*68;                   // 8 x 68
        for (int i = t; i < NN; i += NT){
            cntf[i] = (float)(g_cnt_a[i] + 1);
            als2[i] = g_als2[i];
            ald2[i] = g_ald2[i];
        }
        __syncthreads();
        int n0 = vb*8;
        if (wid < 8) gather_gcn_i(g_hg2, bg2, cntf, smA + wid*68, n0 + wid);
        else         gather_gat_i<false>(g_ha2, als2, ald2, g_c2, bgat2,
                                         smB + (wid-8)*68, n0 + (wid-8));
        __syncthreads();
        {   // mix in place
            int r = t >> 6, c = t & 63;
            smA[r*68 + c] = 0.7f*smA[r*68 + c] + 0.3f*smB[r*68 + c];
        }
        __syncthreads();
        int col = t & 63, row = t >> 6;
        float acc = 0.f;
        #pragma unroll
        for (int k = 0; k < 64; k += 4){
            float w0 = __ldg(Wg3 + (k+0)*64 + col);
            float w1 = __ldg(Wg3 + (k+1)*64 + col);
            float w2 = __ldg(Wg3 + (k+2)*64 + col);
            float w3 = __ldg(Wg3 + (k+3)*64 + col);
            const float4 xv = *reinterpret_cast<const float4*>(smA + row*68 + k);
            acc = fmaf(xv.x, w0, acc);
            acc = fmaf(xv.y, w1, acc);
            acc = fmaf(xv.z, w2, acc);
            acc = fmaf(xv.w, w3, acc);
        }
        g_hg3[(n0 + row)*64 + col] = acc;
    }
    gsync();

    // ===== P3: fused gather3 + predictor GEMM + rowsums (0-127, 8 nodes each) =====
    if (vb < 128){
        float* cntf = (float*)sm;                   // 1024
        float* smH  = (float*)(sm + 4096);          // 8 x 68
        float* sred = smH + 8*68;                   // 16 floats
        for (int i = t; i < NN; i += NT) cntf[i] = (float)(g_cnt_a[i] + 1);
        __syncthreads();
        int n0 = vb*8;
        if (wid < 8) gather_gcn_i(g_hg3, bg3, cntf, smH + wid*68, n0 + wid);
        if (t < 16) sred[t] = 0.f;
        __syncthreads();
        int col = t & 127, rg = t >> 7;             // rows rg, rg+4
        bool hi = col >= 64;
        const float* Wbase = hi ? (Wp1 + 64*64 + (col-64)) : (Wp1 + col);
        float acc0 = 0.f, acc1 = 0.f;
        #pragma unroll
        for (int k = 0; k < 64; k += 2){
            float w0 = __ldg(Wbase + (k+0)*64);
            float w1 = __ldg(Wbase + (k+1)*64);
            float a0 = smH[rg*68 + k],     a1 = smH[rg*68 + k + 1];
            float b0 = smH[(rg+4)*68 + k], b1 = smH[(rg+4)*68 + k + 1];
            acc0 = fmaf(a0, w0, acc0); acc0 = fmaf(a1, w1, acc0);
            acc1 = fmaf(b0, w0, acc1); acc1 = fmaf(b1, w1, acc1);
        }
        float wp2 = __ldg(Wp2 + (col & 63));
        if (!hi){
            float bb = __ldg(bp1 + col);
            acc0 += bb; acc1 += bb;
            g_h1p[(n0 + rg)*64 + col] = acc0;
            g_h1p[(n0 + rg + 4)*64 + col] = acc1;
        } else {
            g_h2pT[(col-64)*NN + n0 + rg] = acc0;
            g_h2pT[(col-64)*NN + n0 + rg + 4] = acc1;
        }
        float p0 = acc0*wp2, p1 = acc1*wp2;
        #pragma unroll
        for (int o = 16; o > 0; o >>= 1){
            p0 += __shfl_down_sync(0xffffffffu, p0, o);
            p1 += __shfl_down_sync(0xffffffffu, p1, o);
        }
        if ((t & 31) == 0){
            int base = hi ? 8 : 0;
            atomicAdd(&sred[base + rg], p0);
            atomicAdd(&sred[base + rg + 4], p1);
        }
        __syncthreads();
        if (t < 8) g_rs1[n0 + t] = sred[t];
        else if (t < 16) g_rs2[n0 + t - 8] = sred[t];
    }
    gsync();

    // ===== P4: all-pairs predictor, 64x128 tiles (0-127); blocks 0,1 also re-zero cnt =====
    if (vb < 2){
        int* cnt = vb ? g_cnt_d : g_cnt_a;
        for (int i = t; i < NN; i += NT) cnt[i] = 0;
    }
    if (vb < 128){
        ull* s1d  = (ull*)sm;                        // [64][65] dup pairs   (33280B)
        ull* s2a  = (ull*)(sm + 33280);              // [64][33] cols 0,1 mod4 (16896B)
        ull* s2b  = (ull*)(sm + 33280 + 16896);      // [64][33] cols 2,3 mod4 (16896B)
        ull* swpd = (ull*)(sm + 33280 + 33792);      // [64] dup 0.5*w       (512B)
        int bi = vb >> 3, bj = vb & 7;
        int i0 = bi*64, j0 = bj*128;
        for (int i = t; i < 1024; i += NT){
            int row = i >> 4, seg = (i & 15)*4;
            float4 v = *(const float4*)(g_h1p + (i0+row)*64 + seg);
            ull* d = s1d + row*65 + seg;
            d[0] = fdup(v.x); d[1] = fdup(v.y); d[2] = fdup(v.z); d[3] = fdup(v.w);
        }
        for (int i = t; i < 2048; i += NT){
            int h = i >> 5, j4 = i & 31;
            float4 v = *(const float4*)(g_h2pT + h*NN + j0 + j4*4);
            s2a[h*33 + j4] = fpack(v.x, v.y);
            s2b[h*33 + j4] = fpack(v.z, v.w);
        }
        if (t < 64) swpd[t] = fdup(0.5f*__ldg(Wp2 + t));
        __syncthreads();

        int tx = t & 31, ty = t >> 5;
        const ull ABS2 = 0x7FFFFFFF7FFFFFFFULL;
        ull acc[4][2];
        #pragma unroll
        for (int a = 0; a < 4; a++){ acc[a][0] = 0ULL; acc[a][1] = 0ULL; }
        const ull* s1p = s1d + (ty*4)*65;

        #pragma unroll 8
        for (int h = 0; h < 64; h++){
            ull w2 = swpd[h];
            ull r2a = s2a[h*33 + tx];
            ull r2b = s2b[h*33 + tx];
            #pragma unroll
            for (int a = 0; a < 4; a++){
                ull r1 = s1p[a*65 + h];
                ull t0 = f2add(r1, r2a) & ABS2;
                ull t1 = f2add(r1, r2b) & ABS2;
                acc[a][0] = f2fma(t0, w2, acc[a][0]);
                acc[a][1] = f2fma(t1, w2, acc[a][1]);
            }
        }
        float bb = bp2[0];
        float hr2[4];
        #pragma unroll
        for (int c = 0; c < 4; c++) hr2[c] = 0.5f*__ldg(g_rs2 + j0 + tx*4 + c);
        #pragma unroll
        for (int a = 0; a < 4; a++){
            int row = i0 + ty*4 + a;
            float base = 0.5f*__ldg(g_rs1 + row) + bb;
            float l0 = f2lo(acc[a][0]) + base + hr2[0];
            float l1 = f2hi(acc[a][0]) + base + hr2[1];
            float l2 = f2lo(acc[a][1]) + base + hr2[2];
            float l3 = f2hi(acc[a][1]) + base + hr2[3];
            float4 o;
            o.x = 1.0f / (1.0f + __expf(-l0));
            o.y = 1.0f / (1.0f + __expf(-l1));
            o.z = 1.0f / (1.0f + __expf(-l2));
            o.w = 1.0f / (1.0f + __expf(-l3));
            *reinterpret_cast<float4*>(out + row*NN + j0 + tx*4) = o;
        }
    }
}

// ---------------- launch ----------------
extern "C" void kernel_launch(void* const* d_in, const int* in_sizes, int n_in,
                              void* d_out, int out_size){
    const float* x    = (const float*)d_in[0];
    const int*   eia  = (const int*)  d_in[1];
    const int*   eid  = (const int*)  d_in[2];
    const float* ew   = (const float*)d_in[3];
    const float* Wg1  = (const float*)d_in[4];
    const float* bg1  = (const float*)d_in[5];
    const float* Wa1  = (const float*)d_in[6];
    const float* as1  = (const float*)d_in[7];
    const float* ad1  = (const float*)d_in[8];
    const float* we1  = (const float*)d_in[9];
    const float* ae1  = (const float*)d_in[10];
    const float* bgat1= (const float*)d_in[11];
    const float* Wg2  = (const float*)d_in[12];
    const float* bg2  = (const float*)d_in[13];
    const float* Wa2  = (const float*)d_in[14];
    const float* as2  = (const float*)d_in[15];
    const float* ad2  = (const float*)d_in[16];
    const float* we2  = (const float*)d_in[17];
    const float* ae2  = (const float*)d_in[18];
    const float* bgat2= (const float*)d_in[19];
    const float* Wg3  = (const float*)d_in[20];
    const float* bg3  = (const float*)d_in[21];
    const float* Wp1  = (const float*)d_in[22];
    const float* bp1  = (const float*)d_in[23];
    const float* Wp2  = (const float*)d_in[24];
    const float* bp2  = (const float*)d_in[25];
    float* out = (float*)d_out;

    const int smem = 33280 + 33792 + 512;   // 67584 bytes (P4 layout is max)
    static int s_attr_done = 0;
    if (!s_attr_done){
        cudaFuncSetAttribute(kmain, cudaFuncAttributeMaxDynamicSharedMemorySize, smem);
        s_attr_done = 1;
    }

    kmain<<<NB, NT, smem>>>(x, eia, eid, ew,
                            Wg1, bg1, Wa1, as1, ad1, we1, ae1, bgat1,
                            Wg2, bg2, Wa2, as2, ad2, we2, ae2, bgat2,
                            Wg3, bg3, Wp1, bp1, Wp2, bp2, out);
}